// round 2
// baseline (speedup 1.0000x reference)
#include <cuda_runtime.h>
#include <cuda_bf16.h>

// Problem constants (fixed by the dataset)
#define B_   2
#define T_   2048
#define DM   1024
#define H_   16
#define HD   64
#define ROWS (B_ * T_)        // 4096

// ---------------- scratch (no cudaMalloc allowed) ----------------
__device__ float g_q[B_ * T_ * DM];
__device__ float g_k[B_ * T_ * DM];
__device__ float g_v[B_ * T_ * DM];
__device__ float g_att[B_ * T_ * DM];

// =================================================================
// SGEMM: C[M,N] = A[M,K] @ B[N,K]^T   (both row-major, K contiguous)
// 128x128 tile, BK=8, 256 threads, 8x8 per thread, register prefetch.
// (measured ~40 TF/s fp32 — at the FFMA roofline; unchanged this round)
// =================================================================
#define BM 128
#define BN 128
#define BK 8

__global__ void __launch_bounds__(256)
sgemm_abt(const float* __restrict__ A, const float* __restrict__ Bm,
          float* __restrict__ C, int M, int N, int K)
{
    __shared__ float As[BK][BM];
    __shared__ float Bs[BK][BN];

    const int bm = blockIdx.y;
    const int bn = blockIdx.x;
    const int tid = threadIdx.x;
    const int tx = tid & 15;
    const int ty = tid >> 4;

    const int arow = tid >> 1;
    const int acol = (tid & 1) * 4;
    const float* Ag = A + (size_t)(bm * BM + arow) * K + acol;
    const float* Bg = Bm + (size_t)(bn * BN + arow) * K + acol;

    float acc[8][8];
#pragma unroll
    for (int i = 0; i < 8; i++)
#pragma unroll
        for (int j = 0; j < 8; j++) acc[i][j] = 0.f;

    float4 a4 = *(const float4*)(Ag);
    float4 b4 = *(const float4*)(Bg);

    for (int k0 = 0; k0 < K; k0 += BK) {
        __syncthreads();
        As[acol + 0][arow] = a4.x;
        As[acol + 1][arow] = a4.y;
        As[acol + 2][arow] = a4.z;
        As[acol + 3][arow] = a4.w;
        Bs[acol + 0][arow] = b4.x;
        Bs[acol + 1][arow] = b4.y;
        Bs[acol + 2][arow] = b4.z;
        Bs[acol + 3][arow] = b4.w;
        __syncthreads();

        if (k0 + BK < K) {
            a4 = *(const float4*)(Ag + k0 + BK);
            b4 = *(const float4*)(Bg + k0 + BK);
        }

#pragma unroll
        for (int kk = 0; kk < BK; kk++) {
            float4 a0 = *(const float4*)&As[kk][ty * 8];
            float4 a1 = *(const float4*)&As[kk][ty * 8 + 4];
            float4 b0 = *(const float4*)&Bs[kk][tx * 8];
            float4 b1 = *(const float4*)&Bs[kk][tx * 8 + 4];
            float ar[8] = {a0.x, a0.y, a0.z, a0.w, a1.x, a1.y, a1.z, a1.w};
            float br[8] = {b0.x, b0.y, b0.z, b0.w, b1.x, b1.y, b1.z, b1.w};
#pragma unroll
            for (int i = 0; i < 8; i++)
#pragma unroll
                for (int j = 0; j < 8; j++)
                    acc[i][j] = fmaf(ar[i], br[j], acc[i][j]);
        }
    }

#pragma unroll
    for (int i = 0; i < 8; i++) {
        int row = bm * BM + ty * 8 + i;
        float* Cr = C + (size_t)row * N + bn * BN + tx * 8;
        *(float4*)Cr       = make_float4(acc[i][0], acc[i][1], acc[i][2], acc[i][3]);
        *(float4*)(Cr + 4) = make_float4(acc[i][4], acc[i][5], acc[i][6], acc[i][7]);
    }
}

// =================================================================
// Flash attention with causal ALiBi — 4 threads per q-row.
// Each thread owns 16 of the 64 dims (oacc: 16 regs, qr: 4x float4).
// QK dot completed via two shfl_xor among the 4 row partners.
// Layout (B, T, H, HD) row-major == (B*T, 1024) GEMM layout.
// =================================================================
#define AT_ROWS    64    // q rows per CTA
#define AT_BN      32    // k rows per smem tile
#define AT_THREADS 256   // 64 rows * 4 parts

__global__ void __launch_bounds__(AT_THREADS, 2)
attn_kernel(const float* __restrict__ q, const float* __restrict__ k,
            const float* __restrict__ v, float* __restrict__ o)
{
    const int h  = blockIdx.y;
    const int b  = blockIdx.z;
    // heavy tiles (large q index) first for better wave packing
    const int i0 = (gridDim.x - 1 - blockIdx.x) * AT_ROWS;
    const int t  = threadIdx.x;
    const int rl = t >> 2;          // local row 0..63
    const int part = t & 3;         // owns dims [part*16, part*16+16)
    const int i  = i0 + rl;

    const float slope = exp2f(-8.0f * (float)(h + 1) / (float)H_);
    const float scale = 0.125f;     // 1/sqrt(64)

    __shared__ float ks[AT_BN][HD];
    __shared__ float vs[AT_BN][HD];

    // this thread's 16 q dims
    float4 qr[4];
    {
        const float4* qrow =
            (const float4*)(q + ((size_t)(b * T_ + i) * H_ + h) * HD + part * 16);
#pragma unroll
        for (int d = 0; d < 4; d++) qr[d] = qrow[d];
    }

    float4 oacc[4];
#pragma unroll
    for (int d = 0; d < 4; d++) oacc[d] = make_float4(0.f, 0.f, 0.f, 0.f);
    float m = -1e30f, l = 0.f;

    const int kend = i0 + AT_ROWS;

    for (int kb0 = 0; kb0 < kend; kb0 += AT_BN) {
        __syncthreads();
        // stage K/V tile: AT_BN x 16 float4 each
        for (int idx = t; idx < AT_BN * (HD / 4); idx += AT_THREADS) {
            int r = idx >> 4;
            int c = idx & 15;
            size_t base = ((size_t)(b * T_ + kb0 + r) * H_ + h) * HD;
            ((float4*)ks[r])[c] = ((const float4*)(k + base))[c];
            ((float4*)vs[r])[c] = ((const float4*)(v + base))[c];
        }
        __syncthreads();

        // warp-uniform predicate: row blocks never split a warp (8 rows/warp,
        // kb0 multiple of 32, row base multiple of 8 -> no divergence here)
        if (kb0 <= i) {
            float s[AT_BN];
            float bmax = m;
#pragma unroll
            for (int j = 0; j < AT_BN; j++) {
                const float4* kj = (const float4*)(&ks[j][part * 16]);
                float a = 0.f;
#pragma unroll
                for (int d = 0; d < 4; d++) {
                    float4 kd = kj[d];
                    a = fmaf(qr[d].x, kd.x, a);
                    a = fmaf(qr[d].y, kd.y, a);
                    a = fmaf(qr[d].z, kd.z, a);
                    a = fmaf(qr[d].w, kd.w, a);
                }
                // complete the 64-dim dot across the 4 row partners
                a += __shfl_xor_sync(0xffffffffu, a, 1);
                a += __shfl_xor_sync(0xffffffffu, a, 2);
                int jj = kb0 + j;
                s[j] = (jj <= i) ? fmaf(-slope, (float)(i - jj), a * scale)
                                 : -1e30f;
                bmax = fmaxf(bmax, s[j]);
            }
            float corr = __expf(m - bmax);
            m = bmax;
            l *= corr;
#pragma unroll
            for (int d = 0; d < 4; d++) {
                oacc[d].x *= corr; oacc[d].y *= corr;
                oacc[d].z *= corr; oacc[d].w *= corr;
            }
#pragma unroll
            for (int j = 0; j < AT_BN; j++) {
                float p = __expf(s[j] - m);
                l += p;
                const float4* vj = (const float4*)(&vs[j][part * 16]);
#pragma unroll
                for (int d = 0; d < 4; d++) {
                    float4 vd = vj[d];
                    oacc[d].x = fmaf(p, vd.x, oacc[d].x);
                    oacc[d].y = fmaf(p, vd.y, oacc[d].y);
                    oacc[d].z = fmaf(p, vd.z, oacc[d].z);
                    oacc[d].w = fmaf(p, vd.w, oacc[d].w);
                }
            }
        }
    }

    float inv = 1.f / l;
    float4* orow = (float4*)(o + ((size_t)(b * T_ + i) * H_ + h) * HD + part * 16);
#pragma unroll
    for (int d = 0; d < 4; d++) {
        float4 tt = oacc[d];
        tt.x *= inv; tt.y *= inv; tt.z *= inv; tt.w *= inv;
        orow[d] = tt;
    }
}

// =================================================================
extern "C" void kernel_launch(void* const* d_in, const int* in_sizes, int n_in,
                              void* d_out, int out_size)
{
    const float* x  = (const float*)d_in[0];
    const float* Wq = (const float*)d_in[1];
    const float* Wk = (const float*)d_in[2];
    const float* Wv = (const float*)d_in[3];
    const float* Wo = (const float*)d_in[4];
    float* out = (float*)d_out;

    float *q, *k, *v, *att;
    cudaGetSymbolAddress((void**)&q,   g_q);
    cudaGetSymbolAddress((void**)&k,   g_k);
    cudaGetSymbolAddress((void**)&v,   g_v);
    cudaGetSymbolAddress((void**)&att, g_att);

    dim3 gblock(256);
    dim3 ggrid(DM / BN, ROWS / BM);   // (8, 32)

    sgemm_abt<<<ggrid, gblock>>>(x, Wq, q, ROWS, DM, DM);
    sgemm_abt<<<ggrid, gblock>>>(x, Wk, k, ROWS, DM, DM);
    sgemm_abt<<<ggrid, gblock>>>(x, Wv, v, ROWS, DM, DM);

    dim3 agrid(T_ / AT_ROWS, H_, B_); // (32, 16, 2) = 1024 CTAs
    attn_kernel<<<agrid, AT_THREADS>>>(q, k, v, att);

    sgemm_abt<<<ggrid, gblock>>>(att, Wo, out, ROWS, DM, DM);
}

// round 3
// speedup vs baseline: 1.9415x; 1.9415x over previous
#include <cuda_runtime.h>
#include <cuda_bf16.h>

// Problem constants (fixed by the dataset)
#define B_   2
#define T_   2048
#define DM   1024
#define H_   16
#define HD   64
#define ROWS (B_ * T_)        // 4096

typedef unsigned long long ull;

// ---- packed fp32x2 ops (Blackwell FFMA2 path; PTX-only, ptxas won't emit) ----
#define FMA_F32X2(out, a, b, c) \
    asm("fma.rn.f32x2 %0, %1, %2, %3;" : "=l"(out) : "l"(a), "l"(b), "l"(c))
#define MUL_F32X2(out, a, b) \
    asm("mul.rn.f32x2 %0, %1, %2;" : "=l"(out) : "l"(a), "l"(b))
#define ADD_F32X2(out, a, b) \
    asm("add.rn.f32x2 %0, %1, %2;" : "=l"(out) : "l"(a), "l"(b))
#define PACK_F32X2(out, lo, hi) \
    asm("mov.b64 %0, {%1, %2};" : "=l"(out) : "r"(lo), "r"(hi))
#define UNPACK_F32X2(lo, hi, in) \
    asm("mov.b64 {%0, %1}, %2;" : "=r"(lo), "=r"(hi) : "l"(in))

__device__ __forceinline__ ull dup_f32(float x) {
    ull r; unsigned u = __float_as_uint(x);
    PACK_F32X2(r, u, u);
    return r;
}

// ---------------- scratch (no cudaMalloc allowed) ----------------
__device__ float g_q[B_ * T_ * DM];
__device__ float g_k[B_ * T_ * DM];
__device__ float g_v[B_ * T_ * DM];
__device__ float g_att[B_ * T_ * DM];

// =================================================================
// SGEMM: C[M,N] = A[M,K] @ B[N,K]^T   (row-major, K contiguous)
// 128x128 tile, BK=8, 256 threads, 8x8 per thread via FFMA2 pairs.
// =================================================================
#define BM 128
#define BN 128
#define BK 8

__global__ void __launch_bounds__(256)
sgemm_abt(const float* __restrict__ A, const float* __restrict__ Bm,
          float* __restrict__ C, int M, int N, int K)
{
    __shared__ float As[BK][BM];
    __shared__ float Bs[BK][BN];

    const int bm = blockIdx.y;
    const int bn = blockIdx.x;
    const int tid = threadIdx.x;
    const int tx = tid & 15;
    const int ty = tid >> 4;

    const int arow = tid >> 1;
    const int acol = (tid & 1) * 4;
    const float* Ag = A + (size_t)(bm * BM + arow) * K + acol;
    const float* Bg = Bm + (size_t)(bn * BN + arow) * K + acol;

    // acc pairs along j: acc2[i][jp] holds columns (2jp, 2jp+1)
    ull acc2[8][4];
#pragma unroll
    for (int i = 0; i < 8; i++)
#pragma unroll
        for (int j = 0; j < 4; j++) acc2[i][j] = 0ull;

    float4 a4 = *(const float4*)(Ag);
    float4 b4 = *(const float4*)(Bg);

    for (int k0 = 0; k0 < K; k0 += BK) {
        __syncthreads();
        As[acol + 0][arow] = a4.x;
        As[acol + 1][arow] = a4.y;
        As[acol + 2][arow] = a4.z;
        As[acol + 3][arow] = a4.w;
        Bs[acol + 0][arow] = b4.x;
        Bs[acol + 1][arow] = b4.y;
        Bs[acol + 2][arow] = b4.z;
        Bs[acol + 3][arow] = b4.w;
        __syncthreads();

        if (k0 + BK < K) {
            a4 = *(const float4*)(Ag + k0 + BK);
            b4 = *(const float4*)(Bg + k0 + BK);
        }

#pragma unroll
        for (int kk = 0; kk < BK; kk++) {
            float4 a0 = *(const float4*)&As[kk][ty * 8];
            float4 a1 = *(const float4*)&As[kk][ty * 8 + 4];
            // b pairs straight out of smem as aligned 64-bit lanes
            const ulonglong2* bp = (const ulonglong2*)&Bs[kk][tx * 8];
            ulonglong2 bb0 = bp[0];
            ulonglong2 bb1 = bp[1];
            ull ad[8];
            ad[0] = dup_f32(a0.x); ad[1] = dup_f32(a0.y);
            ad[2] = dup_f32(a0.z); ad[3] = dup_f32(a0.w);
            ad[4] = dup_f32(a1.x); ad[5] = dup_f32(a1.y);
            ad[6] = dup_f32(a1.z); ad[7] = dup_f32(a1.w);
#pragma unroll
            for (int i = 0; i < 8; i++) {
                FMA_F32X2(acc2[i][0], ad[i], bb0.x, acc2[i][0]);
                FMA_F32X2(acc2[i][1], ad[i], bb0.y, acc2[i][1]);
                FMA_F32X2(acc2[i][2], ad[i], bb1.x, acc2[i][2]);
                FMA_F32X2(acc2[i][3], ad[i], bb1.y, acc2[i][3]);
            }
        }
    }

#pragma unroll
    for (int i = 0; i < 8; i++) {
        int row = bm * BM + ty * 8 + i;
        float* Cr = C + (size_t)row * N + bn * BN + tx * 8;
        ulonglong2 c0, c1;
        c0.x = acc2[i][0]; c0.y = acc2[i][1];
        c1.x = acc2[i][2]; c1.y = acc2[i][3];
        *(ulonglong2*)Cr       = c0;
        *((ulonglong2*)Cr + 1) = c1;
    }
}

// =================================================================
// Flash attention with causal ALiBi — 1 thread per q-row (R1 layout),
// inner loops on FFMA2. Softmax scalar path runs once per row.
// q,k,v,o layout: (B, T, H, HD) row-major.
// =================================================================
#define AT_BM 128
#define AT_BN 32

__global__ void __launch_bounds__(AT_BM)
attn_kernel(const float* __restrict__ q, const float* __restrict__ k,
            const float* __restrict__ v, float* __restrict__ o)
{
    const int h = blockIdx.y;
    const int b = blockIdx.z;
    // heavy tiles (large q index) first for wave packing
    const int i0 = (gridDim.x - 1 - blockIdx.x) * AT_BM;
    const int i = i0 + threadIdx.x;

    const float slope = exp2f(-8.0f * (float)(h + 1) / (float)H_);
    const float scale = 0.125f;  // 1/sqrt(64)

    __shared__ float ks[AT_BN][HD];
    __shared__ float vs[AT_BN][HD];

    // q row -> 32 packed fp32 pairs
    ull q2[32];
    {
        const ulonglong2* qrow =
            (const ulonglong2*)(q + ((size_t)(b * T_ + i) * H_ + h) * HD);
#pragma unroll
        for (int d = 0; d < 16; d++) {
            ulonglong2 t = qrow[d];
            q2[2 * d] = t.x;
            q2[2 * d + 1] = t.y;
        }
    }

    ull o2[32];
#pragma unroll
    for (int d = 0; d < 32; d++) o2[d] = 0ull;
    float m = -1e30f, l = 0.f;

    const int kend = i0 + AT_BM;

    for (int kb0 = 0; kb0 < kend; kb0 += AT_BN) {
        __syncthreads();
        // stage K/V tile: AT_BN x 16 float4 each
        for (int idx = threadIdx.x; idx < AT_BN * (HD / 4); idx += AT_BM) {
            int r = idx >> 4;
            int c = idx & 15;
            size_t base = ((size_t)(b * T_ + kb0 + r) * H_ + h) * HD;
            ((float4*)ks[r])[c] = ((const float4*)(k + base))[c];
            ((float4*)vs[r])[c] = ((const float4*)(v + base))[c];
        }
        __syncthreads();

        if (kb0 <= i) {
            float s[AT_BN];
            float bmax = m;
#pragma unroll
            for (int j = 0; j < AT_BN; j++) {
                const ulonglong2* kj = (const ulonglong2*)ks[j];
                ull accA[4] = {0ull, 0ull, 0ull, 0ull};
#pragma unroll
                for (int d = 0; d < 16; d++) {
                    ulonglong2 t = kj[d];
                    FMA_F32X2(accA[(2 * d) & 3],     q2[2 * d],     t.x, accA[(2 * d) & 3]);
                    FMA_F32X2(accA[(2 * d + 1) & 3], q2[2 * d + 1], t.y, accA[(2 * d + 1) & 3]);
                }
                ADD_F32X2(accA[0], accA[0], accA[1]);
                ADD_F32X2(accA[2], accA[2], accA[3]);
                ADD_F32X2(accA[0], accA[0], accA[2]);
                unsigned alo, ahi;
                UNPACK_F32X2(alo, ahi, accA[0]);
                float a = __uint_as_float(alo) + __uint_as_float(ahi);
                int jj = kb0 + j;
                s[j] = (jj <= i) ? fmaf(-slope, (float)(i - jj), a * scale)
                                 : -1e30f;
                bmax = fmaxf(bmax, s[j]);
            }
            float corr = __expf(m - bmax);
            m = bmax;
            l *= corr;
            ull corr2 = dup_f32(corr);
#pragma unroll
            for (int d = 0; d < 32; d++) MUL_F32X2(o2[d], o2[d], corr2);
#pragma unroll
            for (int j = 0; j < AT_BN; j++) {
                float p = __expf(s[j] - m);
                l += p;
                ull p2 = dup_f32(p);
                const ulonglong2* vj = (const ulonglong2*)vs[j];
#pragma unroll
                for (int d = 0; d < 16; d++) {
                    ulonglong2 t = vj[d];
                    FMA_F32X2(o2[2 * d],     p2, t.x, o2[2 * d]);
                    FMA_F32X2(o2[2 * d + 1], p2, t.y, o2[2 * d + 1]);
                }
            }
        }
    }

    float inv = 1.f / l;
    ull inv2 = dup_f32(inv);
    ulonglong2* orow =
        (ulonglong2*)(o + ((size_t)(b * T_ + i) * H_ + h) * HD);
#pragma unroll
    for (int d = 0; d < 16; d++) {
        ulonglong2 t;
        MUL_F32X2(t.x, o2[2 * d],     inv2);
        MUL_F32X2(t.y, o2[2 * d + 1], inv2);
        orow[d] = t;
    }
}

// =================================================================
extern "C" void kernel_launch(void* const* d_in, const int* in_sizes, int n_in,
                              void* d_out, int out_size)
{
    const float* x  = (const float*)d_in[0];
    const float* Wq = (const float*)d_in[1];
    const float* Wk = (const float*)d_in[2];
    const float* Wv = (const float*)d_in[3];
    const float* Wo = (const float*)d_in[4];
    float* out = (float*)d_out;

    float *q, *k, *v, *att;
    cudaGetSymbolAddress((void**)&q,   g_q);
    cudaGetSymbolAddress((void**)&k,   g_k);
    cudaGetSymbolAddress((void**)&v,   g_v);
    cudaGetSymbolAddress((void**)&att, g_att);

    dim3 gblock(256);
    dim3 ggrid(DM / BN, ROWS / BM);   // (8, 32)

    sgemm_abt<<<ggrid, gblock>>>(x, Wq, q, ROWS, DM, DM);
    sgemm_abt<<<ggrid, gblock>>>(x, Wk, k, ROWS, DM, DM);
    sgemm_abt<<<ggrid, gblock>>>(x, Wv, v, ROWS, DM, DM);

    dim3 agrid(T_ / AT_BM, H_, B_);   // (16, 16, 2)
    attn_kernel<<<agrid, AT_BM>>>(q, k, v, att);

    sgemm_abt<<<ggrid, gblock>>>(att, Wo, out, ROWS, DM, DM);
}

// round 5
// speedup vs baseline: 2.7523x; 1.4176x over previous
#include <cuda_runtime.h>
#include <cuda_bf16.h>
#include <cstdint>

// Problem constants (fixed by the dataset)
#define B_   2
#define T_   2048
#define DM   1024
#define H_   16
#define HD   64
#define ROWS (B_ * T_)        // 4096

typedef unsigned long long ull;

// ---- packed fp32x2 (FFMA2) helpers for the attention kernel ----
#define FMA_F32X2(out, a, b, c) \
    asm("fma.rn.f32x2 %0, %1, %2, %3;" : "=l"(out) : "l"(a), "l"(b), "l"(c))
#define MUL_F32X2(out, a, b) \
    asm("mul.rn.f32x2 %0, %1, %2;" : "=l"(out) : "l"(a), "l"(b))
#define ADD_F32X2(out, a, b) \
    asm("add.rn.f32x2 %0, %1, %2;" : "=l"(out) : "l"(a), "l"(b))
#define PACK_F32X2(out, lo, hi) \
    asm("mov.b64 %0, {%1, %2};" : "=l"(out) : "r"(lo), "r"(hi))
#define UNPACK_F32X2(lo, hi, in) \
    asm("mov.b64 {%0, %1}, %2;" : "=r"(lo), "=r"(hi) : "l"(in))

__device__ __forceinline__ ull dup_f32(float x) {
    ull r; unsigned u = __float_as_uint(x);
    PACK_F32X2(r, u, u);
    return r;
}

// ---------------- scratch (no cudaMalloc allowed) ----------------
__device__ float g_q[ROWS * DM];
__device__ float g_k[ROWS * DM];
__device__ float g_v[ROWS * DM];
__device__ float g_att[ROWS * DM];
__device__ __nv_bfloat16 g_ahi[ROWS * DM];   // x / att  hi
__device__ __nv_bfloat16 g_alo[ROWS * DM];   // x / att  lo
__device__ __nv_bfloat16 g_whi[DM * DM];     // current W hi
__device__ __nv_bfloat16 g_wlo[DM * DM];     // current W lo

// =================================================================
// helpers
// =================================================================
__device__ __forceinline__ uint32_t smem_u32(const void* p) {
    uint32_t a;
    asm("{ .reg .u64 t; cvta.to.shared.u64 t, %1; cvt.u32.u64 %0, t; }"
        : "=r"(a) : "l"(p));
    return a;
}
__device__ __forceinline__ void cp16(uint32_t dst, const void* src) {
    asm volatile("cp.async.cg.shared.global [%0], [%1], 16;" :: "r"(dst), "l"(src));
}
#define CP_COMMIT() asm volatile("cp.async.commit_group;")

__device__ __forceinline__ void ldsm4(uint32_t (&r)[4], uint32_t addr) {
    asm volatile("ldmatrix.sync.aligned.m8n8.x4.shared.b16 {%0,%1,%2,%3}, [%4];"
                 : "=r"(r[0]), "=r"(r[1]), "=r"(r[2]), "=r"(r[3]) : "r"(addr));
}
__device__ __forceinline__ void mma_bf16(float (&d)[4], const uint32_t (&a)[4],
                                         uint32_t b0, uint32_t b1) {
    asm volatile(
        "mma.sync.aligned.m16n8k16.row.col.f32.bf16.bf16.f32 "
        "{%0,%1,%2,%3}, {%4,%5,%6,%7}, {%8,%9}, {%0,%1,%2,%3};"
        : "+f"(d[0]), "+f"(d[1]), "+f"(d[2]), "+f"(d[3])
        : "r"(a[0]), "r"(a[1]), "r"(a[2]), "r"(a[3]), "r"(b0), "r"(b1));
}

// =================================================================
// HMMA split-bf16 GEMM: C[4096,1024] = A @ W^T (both K-contiguous).
// CTA 128x128, BK=64, 8 warps of 64x32, double-buffered cp.async,
// XOR-swizzled smem, 3 passes: Ahi*Whi + Ahi*Wlo + Alo*Whi.
// =================================================================
#define GBK      64
#define NKC      (DM / GBK)     // 16
#define TILE_B   (128 * 128)    // 16 KB per 128x64-bf16 tile
#define STAGE_B  (4 * TILE_B)   // Ahi, Alo, Whi, Wlo
#define GEMM_SMEM (2 * STAGE_B) // 128 KB

__device__ __forceinline__ void load_tile(uint32_t dst, const __nv_bfloat16* g,
                                          int row0, int k0, int tid) {
    const char* gb = (const char*)(g + (size_t)row0 * DM + k0);
#pragma unroll
    for (int it = 0; it < 4; it++) {
        int idx = tid + it * 256;            // 0..1023
        int r = idx >> 3;                    // 0..127
        int c = idx & 7;                     // 16B chunk
        uint32_t sw = (uint32_t)(r * 128 + ((c ^ (r & 7)) << 4));
        cp16(dst + sw, gb + (size_t)r * DM * 2 + c * 16);
    }
}

__global__ void __launch_bounds__(256, 1)
mma_split_gemm(const __nv_bfloat16* __restrict__ Ahi,
               const __nv_bfloat16* __restrict__ Alo,
               const __nv_bfloat16* __restrict__ Whi,
               const __nv_bfloat16* __restrict__ Wlo,
               float* __restrict__ C)
{
    extern __shared__ char smraw[];
    const uint32_t sb = smem_u32(smraw);
    const int tid = threadIdx.x;
    const int wid = tid >> 5;
    const int lane = tid & 31;
    const int wm = wid >> 2;          // 0..1 (64-row slab)
    const int wn = wid & 3;           // 0..3 (32-col slab)
    const int n0 = blockIdx.x * 128;
    const int m0 = blockIdx.y * 128;

    const int lrow = lane & 15;
    const int lsel = lane >> 4;       // chunk select for ldmatrix x4

    // per-lane tile row indices
    int arow[4], brow[2];
#pragma unroll
    for (int mf = 0; mf < 4; mf++) arow[mf] = wm * 64 + mf * 16 + lrow;
#pragma unroll
    for (int nf = 0; nf < 2; nf++) brow[nf] = wn * 32 + nf * 16 + lrow;

    float acc[4][4][4];
#pragma unroll
    for (int i = 0; i < 4; i++)
#pragma unroll
        for (int j = 0; j < 4; j++)
#pragma unroll
            for (int e = 0; e < 4; e++) acc[i][j][e] = 0.f;

    auto stage = [&](int s) { return sb + s * STAGE_B; };

    // prologue
    load_tile(stage(0) + 0 * TILE_B, Ahi, m0, 0, tid);
    load_tile(stage(0) + 1 * TILE_B, Alo, m0, 0, tid);
    load_tile(stage(0) + 2 * TILE_B, Whi, n0, 0, tid);
    load_tile(stage(0) + 3 * TILE_B, Wlo, n0, 0, tid);
    CP_COMMIT();

    for (int kc = 0; kc < NKC; kc++) {
        int s = kc & 1;
        if (kc + 1 < NKC) {
            int k0 = (kc + 1) * GBK;
            load_tile(stage(s ^ 1) + 0 * TILE_B, Ahi, m0, k0, tid);
            load_tile(stage(s ^ 1) + 1 * TILE_B, Alo, m0, k0, tid);
            load_tile(stage(s ^ 1) + 2 * TILE_B, Whi, n0, k0, tid);
            load_tile(stage(s ^ 1) + 3 * TILE_B, Wlo, n0, k0, tid);
            CP_COMMIT();
            asm volatile("cp.async.wait_group 1;");
        } else {
            asm volatile("cp.async.wait_group 0;");
        }
        __syncthreads();

        const uint32_t sAh = stage(s) + 0 * TILE_B;
        const uint32_t sAl = stage(s) + 1 * TILE_B;
        const uint32_t sWh = stage(s) + 2 * TILE_B;
        const uint32_t sWl = stage(s) + 3 * TILE_B;

#pragma unroll
        for (int t = 0; t < 4; t++) {     // 4 x k16 per chunk
            const int c0 = t * 2;
            uint32_t ah[4][4], al[4][4];
#pragma unroll
            for (int mf = 0; mf < 4; mf++) {
                int r = arow[mf];
                uint32_t off = (uint32_t)(r * 128 +
                                (((c0 + lsel) ^ (r & 7)) << 4));
                ldsm4(ah[mf], sAh + off);
                ldsm4(al[mf], sAl + off);
            }
            uint32_t bh[2][4], bl[2][4];
#pragma unroll
            for (int nf = 0; nf < 2; nf++) {
                int r = brow[nf];
                uint32_t off = (uint32_t)(r * 128 +
                                (((c0 + lsel) ^ (r & 7)) << 4));
                ldsm4(bh[nf], sWh + off);
                ldsm4(bl[nf], sWl + off);
            }
            // bh[nf] = {f(2nf).r0, f(2nf+1).r0, f(2nf).r1, f(2nf+1).r1}
#pragma unroll
            for (int mf = 0; mf < 4; mf++) {
#pragma unroll
                for (int nf = 0; nf < 2; nf++) {
                    mma_bf16(acc[mf][2 * nf],     ah[mf], bh[nf][0], bh[nf][2]);
                    mma_bf16(acc[mf][2 * nf + 1], ah[mf], bh[nf][1], bh[nf][3]);
                    mma_bf16(acc[mf][2 * nf],     ah[mf], bl[nf][0], bl[nf][2]);
                    mma_bf16(acc[mf][2 * nf + 1], ah[mf], bl[nf][1], bl[nf][3]);
                    mma_bf16(acc[mf][2 * nf],     al[mf], bh[nf][0], bh[nf][2]);
                    mma_bf16(acc[mf][2 * nf + 1], al[mf], bh[nf][1], bh[nf][3]);
                }
            }
        }
        __syncthreads();
    }

    // epilogue: lane owns rows (l>>2, l>>2 + 8) cols 2*(l&3)..+1 per frag
    const int erow = m0 + wm * 64 + (lane >> 2);
    const int ecol = n0 + wn * 32 + (lane & 3) * 2;
#pragma unroll
    for (int mf = 0; mf < 4; mf++) {
#pragma unroll
        for (int nf = 0; nf < 4; nf++) {
            float* p0 = C + (size_t)(erow + mf * 16) * DM + ecol + nf * 8;
            float* p1 = p0 + 8 * DM;
            *(float2*)p0 = make_float2(acc[mf][nf][0], acc[mf][nf][1]);
            *(float2*)p1 = make_float2(acc[mf][nf][2], acc[mf][nf][3]);
        }
    }
}

// =================================================================
// fp32 -> (bf16 hi, bf16 lo) split
// =================================================================
__global__ void __launch_bounds__(256)
split_bf16(const float* __restrict__ in, __nv_bfloat16* __restrict__ hi,
           __nv_bfloat16* __restrict__ lo, int n4)
{
    int i = blockIdx.x * blockDim.x + threadIdx.x;
    if (i >= n4) return;
    float4 x = ((const float4*)in)[i];
    __nv_bfloat16 h0 = __float2bfloat16(x.x);
    __nv_bfloat16 h1 = __float2bfloat16(x.y);
    __nv_bfloat16 h2 = __float2bfloat16(x.z);
    __nv_bfloat16 h3 = __float2bfloat16(x.w);
    __nv_bfloat162 hh0; hh0.x = h0; hh0.y = h1;
    __nv_bfloat162 hh1; hh1.x = h2; hh1.y = h3;
    ((__nv_bfloat162*)hi)[2 * i]     = hh0;
    ((__nv_bfloat162*)hi)[2 * i + 1] = hh1;
    __nv_bfloat162 ll0, ll1;
    ll0.x = __float2bfloat16(x.x - __bfloat162float(h0));
    ll0.y = __float2bfloat16(x.y - __bfloat162float(h1));
    ll1.x = __float2bfloat16(x.z - __bfloat162float(h2));
    ll1.y = __float2bfloat16(x.w - __bfloat162float(h3));
    ((__nv_bfloat162*)lo)[2 * i]     = ll0;
    ((__nv_bfloat162*)lo)[2 * i + 1] = ll1;
}

// =================================================================
// Flash attention with causal ALiBi (R3 version, FFMA2 inner loops)
// q,k,v,o layout: (B, T, H, HD) row-major.
// =================================================================
#define AT_BM 128
#define AT_BN 32

__global__ void __launch_bounds__(AT_BM)
attn_kernel(const float* __restrict__ q, const float* __restrict__ k,
            const float* __restrict__ v, float* __restrict__ o)
{
    const int h = blockIdx.y;
    const int b = blockIdx.z;
    const int i0 = (gridDim.x - 1 - blockIdx.x) * AT_BM;
    const int i = i0 + threadIdx.x;

    const float slope = exp2f(-8.0f * (float)(h + 1) / (float)H_);
    const float scale = 0.125f;

    __shared__ float ks[AT_BN][HD];
    __shared__ float vs[AT_BN][HD];

    ull q2[32];
    {
        const ulonglong2* qrow =
            (const ulonglong2*)(q + ((size_t)(b * T_ + i) * H_ + h) * HD);
#pragma unroll
        for (int d = 0; d < 16; d++) {
            ulonglong2 t = qrow[d];
            q2[2 * d] = t.x;
            q2[2 * d + 1] = t.y;
        }
    }

    ull o2[32];
#pragma unroll
    for (int d = 0; d < 32; d++) o2[d] = 0ull;
    float m = -1e30f, l = 0.f;

    const int kend = i0 + AT_BM;

    for (int kb0 = 0; kb0 < kend; kb0 += AT_BN) {
        __syncthreads();
        for (int idx = threadIdx.x; idx < AT_BN * (HD / 4); idx += AT_BM) {
            int r = idx >> 4;
            int c = idx & 15;
            size_t base = ((size_t)(b * T_ + kb0 + r) * H_ + h) * HD;
            ((float4*)ks[r])[c] = ((const float4*)(k + base))[c];
            ((float4*)vs[r])[c] = ((const float4*)(v + base))[c];
        }
        __syncthreads();

        if (kb0 <= i) {
            float s[AT_BN];
            float bmax = m;
#pragma unroll
            for (int j = 0; j < AT_BN; j++) {
                const ulonglong2* kj = (const ulonglong2*)ks[j];
                ull accA[4] = {0ull, 0ull, 0ull, 0ull};
#pragma unroll
                for (int d = 0; d < 16; d++) {
                    ulonglong2 t = kj[d];
                    FMA_F32X2(accA[(2 * d) & 3],     q2[2 * d],     t.x, accA[(2 * d) & 3]);
                    FMA_F32X2(accA[(2 * d + 1) & 3], q2[2 * d + 1], t.y, accA[(2 * d + 1) & 3]);
                }
                ADD_F32X2(accA[0], accA[0], accA[1]);
                ADD_F32X2(accA[2], accA[2], accA[3]);
                ADD_F32X2(accA[0], accA[0], accA[2]);
                unsigned alo, ahi;
                UNPACK_F32X2(alo, ahi, accA[0]);
                float a = __uint_as_float(alo) + __uint_as_float(ahi);
                int jj = kb0 + j;
                s[j] = (jj <= i) ? fmaf(-slope, (float)(i - jj), a * scale)
                                 : -1e30f;
                bmax = fmaxf(bmax, s[j]);
            }
            float corr = __expf(m - bmax);
            m = bmax;
            l *= corr;
            ull corr2 = dup_f32(corr);
#pragma unroll
            for (int d = 0; d < 32; d++) MUL_F32X2(o2[d], o2[d], corr2);
#pragma unroll
            for (int j = 0; j < AT_BN; j++) {
                float p = __expf(s[j] - m);
                l += p;
                ull p2 = dup_f32(p);
                const ulonglong2* vj = (const ulonglong2*)vs[j];
#pragma unroll
                for (int d = 0; d < 16; d++) {
                    ulonglong2 t = vj[d];
                    FMA_F32X2(o2[2 * d],     p2, t.x, o2[2 * d]);
                    FMA_F32X2(o2[2 * d + 1], p2, t.y, o2[2 * d + 1]);
                }
            }
        }
    }

    float inv = 1.f / l;
    ull inv2 = dup_f32(inv);
    ulonglong2* orow = (ulonglong2*)(o + ((size_t)(b * T_ + i) * H_ + h) * HD);
#pragma unroll
    for (int d = 0; d < 16; d++) {
        ulonglong2 t;
        MUL_F32X2(t.x, o2[2 * d],     inv2);
        MUL_F32X2(t.y, o2[2 * d + 1], inv2);
        orow[d] = t;
    }
}

// =================================================================
extern "C" void kernel_launch(void* const* d_in, const int* in_sizes, int n_in,
                              void* d_out, int out_size)
{
    const float* x  = (const float*)d_in[0];
    const float* Wq = (const float*)d_in[1];
    const float* Wk = (const float*)d_in[2];
    const float* Wv = (const float*)d_in[3];
    const float* Wo = (const float*)d_in[4];
    float* out = (float*)d_out;

    float *q, *k, *v, *att;
    __nv_bfloat16 *ahi, *alo, *whi, *wlo;
    cudaGetSymbolAddress((void**)&q,   g_q);
    cudaGetSymbolAddress((void**)&k,   g_k);
    cudaGetSymbolAddress((void**)&v,   g_v);
    cudaGetSymbolAddress((void**)&att, g_att);
    cudaGetSymbolAddress((void**)&ahi, g_ahi);
    cudaGetSymbolAddress((void**)&alo, g_alo);
    cudaGetSymbolAddress((void**)&whi, g_whi);
    cudaGetSymbolAddress((void**)&wlo, g_wlo);

    cudaFuncSetAttribute(mma_split_gemm,
                         cudaFuncAttributeMaxDynamicSharedMemorySize, GEMM_SMEM);

    const int nx4 = ROWS * DM / 4;
    const int nw4 = DM * DM / 4;
    dim3 ggrid(DM / 128, ROWS / 128);  // (8, 32)

    // x -> hi/lo once
    split_bf16<<<(nx4 + 255) / 256, 256>>>(x, ahi, alo, nx4);

    split_bf16<<<(nw4 + 255) / 256, 256>>>(Wq, whi, wlo, nw4);
    mma_split_gemm<<<ggrid, 256, GEMM_SMEM>>>(ahi, alo, whi, wlo, q);
    split_bf16<<<(nw4 + 255) / 256, 256>>>(Wk, whi, wlo, nw4);
    mma_split_gemm<<<ggrid, 256, GEMM_SMEM>>>(ahi, alo, whi, wlo, k);
    split_bf16<<<(nw4 + 255) / 256, 256>>>(Wv, whi, wlo, nw4);
    mma_split_gemm<<<ggrid, 256, GEMM_SMEM>>>(ahi, alo, whi, wlo, v);

    dim3 agrid(T_ / AT_BM, H_, B_);   // (16, 16, 2)
    attn_kernel<<<agrid, AT_BM>>>(q, k, v, att);

    split_bf16<<<(nx4 + 255) / 256, 256>>>(att, ahi, alo, nx4);
    split_bf16<<<(nw4 + 255) / 256, 256>>>(Wo, whi, wlo, nw4);
    mma_split_gemm<<<ggrid, 256, GEMM_SMEM>>>(ahi, alo, whi, wlo, out);
}

// round 6
// speedup vs baseline: 5.8398x; 2.1218x over previous
#include <cuda_runtime.h>
#include <cuda_bf16.h>
#include <cstdint>

#define B_   2
#define T_   2048
#define DM   1024
#define H_   16
#define HD   64
#define ROWS (B_ * T_)        // 4096

// ---------------- scratch (no cudaMalloc allowed) ----------------
__device__ __nv_bfloat16 g_xhi[ROWS * DM];
__device__ __nv_bfloat16 g_xlo[ROWS * DM];
__device__ __nv_bfloat16 g_whi[DM * DM];
__device__ __nv_bfloat16 g_wlo[DM * DM];
__device__ __nv_bfloat16 g_qhi[ROWS * DM];
__device__ __nv_bfloat16 g_qlo[ROWS * DM];
__device__ __nv_bfloat16 g_khi[ROWS * DM];
__device__ __nv_bfloat16 g_klo[ROWS * DM];
__device__ __nv_bfloat16 g_vhi[ROWS * DM];
__device__ __nv_bfloat16 g_vlo[ROWS * DM];
__device__ __nv_bfloat16 g_ohi[ROWS * DM];
__device__ __nv_bfloat16 g_olo[ROWS * DM];

// =================================================================
// low-level helpers
// =================================================================
__device__ __forceinline__ uint32_t smem_u32(const void* p) {
    uint32_t a;
    asm("{ .reg .u64 t; cvta.to.shared.u64 t, %1; cvt.u32.u64 %0, t; }"
        : "=r"(a) : "l"(p));
    return a;
}
__device__ __forceinline__ void cp16(uint32_t dst, const void* src) {
    asm volatile("cp.async.cg.shared.global [%0], [%1], 16;" :: "r"(dst), "l"(src));
}
#define CP_COMMIT() asm volatile("cp.async.commit_group;")

__device__ __forceinline__ void ldsm4(uint32_t (&r)[4], uint32_t addr) {
    asm volatile("ldmatrix.sync.aligned.m8n8.x4.shared.b16 {%0,%1,%2,%3}, [%4];"
                 : "=r"(r[0]), "=r"(r[1]), "=r"(r[2]), "=r"(r[3]) : "r"(addr));
}
__device__ __forceinline__ void ldsm4t(uint32_t (&r)[4], uint32_t addr) {
    asm volatile("ldmatrix.sync.aligned.m8n8.x4.trans.shared.b16 {%0,%1,%2,%3}, [%4];"
                 : "=r"(r[0]), "=r"(r[1]), "=r"(r[2]), "=r"(r[3]) : "r"(addr));
}
__device__ __forceinline__ void mma_bf16(float (&d)[4], const uint32_t (&a)[4],
                                         uint32_t b0, uint32_t b1) {
    asm volatile(
        "mma.sync.aligned.m16n8k16.row.col.f32.bf16.bf16.f32 "
        "{%0,%1,%2,%3}, {%4,%5,%6,%7}, {%8,%9}, {%0,%1,%2,%3};"
        : "+f"(d[0]), "+f"(d[1]), "+f"(d[2]), "+f"(d[3])
        : "r"(a[0]), "r"(a[1]), "r"(a[2]), "r"(a[3]), "r"(b0), "r"(b1));
}
__device__ __forceinline__ float ex2(float x) {
    float y;
    asm("ex2.approx.ftz.f32 %0, %1;" : "=f"(y) : "f"(x));
    return y;
}
// split two fp32 into (bf16x2 hi, bf16x2 lo) with residual correction
__device__ __forceinline__ void split2(float c0, float c1,
                                       uint32_t& hi2, uint32_t& lo2) {
    asm("cvt.rn.bf16x2.f32 %0, %1, %2;" : "=r"(hi2) : "f"(c1), "f"(c0));
    float h0 = __uint_as_float(hi2 << 16);
    float h1 = __uint_as_float(hi2 & 0xffff0000u);
    float r0 = c0 - h0, r1 = c1 - h1;
    asm("cvt.rn.bf16x2.f32 %0, %1, %2;" : "=r"(lo2) : "f"(r1), "f"(r0));
}
// swizzled offset inside a 128B-row tile (r = row, c = 16B chunk 0..7)
__device__ __forceinline__ uint32_t swz(int r, int c) {
    return (uint32_t)(r * 128 + ((c ^ (r & 7)) << 4));
}

// =================================================================
// HMMA split-bf16 GEMM: C[4096,1024] = A @ W^T (both K-contiguous).
// MODE 0: fp32 C.  MODE 1: bf16 hi/lo C (feeds attention / next GEMM).
// =================================================================
#define GBK      64
#define NKC      (DM / GBK)     // 16
#define TILE_B   (128 * 128)    // 16 KB per 128x64-bf16 tile
#define STAGE_B  (4 * TILE_B)
#define GEMM_SMEM (2 * STAGE_B) // 128 KB

__device__ __forceinline__ void load_tile(uint32_t dst, const __nv_bfloat16* g,
                                          int row0, int k0, int tid) {
    const char* gb = (const char*)(g + (size_t)row0 * DM + k0);
#pragma unroll
    for (int it = 0; it < 4; it++) {
        int idx = tid + it * 256;
        int r = idx >> 3;
        int c = idx & 7;
        cp16(dst + swz(r, c), gb + (size_t)r * DM * 2 + c * 16);
    }
}

template<int MODE>
__global__ void __launch_bounds__(256, 1)
mma_split_gemm(const __nv_bfloat16* __restrict__ Ahi,
               const __nv_bfloat16* __restrict__ Alo,
               const __nv_bfloat16* __restrict__ Whi,
               const __nv_bfloat16* __restrict__ Wlo,
               float* __restrict__ Cf,
               __nv_bfloat16* __restrict__ Chi,
               __nv_bfloat16* __restrict__ Clo)
{
    extern __shared__ char smraw[];
    const uint32_t sb = smem_u32(smraw);
    const int tid = threadIdx.x;
    const int wid = tid >> 5;
    const int lane = tid & 31;
    const int wm = wid >> 2;
    const int wn = wid & 3;
    const int n0 = blockIdx.x * 128;
    const int m0 = blockIdx.y * 128;

    const int lrow = lane & 15;
    const int lsel = lane >> 4;

    int arow[4], brow[2];
#pragma unroll
    for (int mf = 0; mf < 4; mf++) arow[mf] = wm * 64 + mf * 16 + lrow;
#pragma unroll
    for (int nf = 0; nf < 2; nf++) brow[nf] = wn * 32 + nf * 16 + lrow;

    float acc[4][4][4];
#pragma unroll
    for (int i = 0; i < 4; i++)
#pragma unroll
        for (int j = 0; j < 4; j++)
#pragma unroll
            for (int e = 0; e < 4; e++) acc[i][j][e] = 0.f;

    auto stage = [&](int s) { return sb + s * STAGE_B; };

    load_tile(stage(0) + 0 * TILE_B, Ahi, m0, 0, tid);
    load_tile(stage(0) + 1 * TILE_B, Alo, m0, 0, tid);
    load_tile(stage(0) + 2 * TILE_B, Whi, n0, 0, tid);
    load_tile(stage(0) + 3 * TILE_B, Wlo, n0, 0, tid);
    CP_COMMIT();

    for (int kc = 0; kc < NKC; kc++) {
        int s = kc & 1;
        if (kc + 1 < NKC) {
            int k0 = (kc + 1) * GBK;
            load_tile(stage(s ^ 1) + 0 * TILE_B, Ahi, m0, k0, tid);
            load_tile(stage(s ^ 1) + 1 * TILE_B, Alo, m0, k0, tid);
            load_tile(stage(s ^ 1) + 2 * TILE_B, Whi, n0, k0, tid);
            load_tile(stage(s ^ 1) + 3 * TILE_B, Wlo, n0, k0, tid);
            CP_COMMIT();
            asm volatile("cp.async.wait_group 1;");
        } else {
            asm volatile("cp.async.wait_group 0;");
        }
        __syncthreads();

        const uint32_t sAh = stage(s) + 0 * TILE_B;
        const uint32_t sAl = stage(s) + 1 * TILE_B;
        const uint32_t sWh = stage(s) + 2 * TILE_B;
        const uint32_t sWl = stage(s) + 3 * TILE_B;

#pragma unroll
        for (int t = 0; t < 4; t++) {
            const int c0 = t * 2;
            uint32_t ah[4][4], al[4][4];
#pragma unroll
            for (int mf = 0; mf < 4; mf++) {
                int r = arow[mf];
                uint32_t off = (uint32_t)(r * 128 + (((c0 + lsel) ^ (r & 7)) << 4));
                ldsm4(ah[mf], sAh + off);
                ldsm4(al[mf], sAl + off);
            }
            uint32_t bh[2][4], bl[2][4];
#pragma unroll
            for (int nf = 0; nf < 2; nf++) {
                int r = brow[nf];
                uint32_t off = (uint32_t)(r * 128 + (((c0 + lsel) ^ (r & 7)) << 4));
                ldsm4(bh[nf], sWh + off);
                ldsm4(bl[nf], sWl + off);
            }
#pragma unroll
            for (int mf = 0; mf < 4; mf++) {
#pragma unroll
                for (int nf = 0; nf < 2; nf++) {
                    mma_bf16(acc[mf][2 * nf],     ah[mf], bh[nf][0], bh[nf][2]);
                    mma_bf16(acc[mf][2 * nf + 1], ah[mf], bh[nf][1], bh[nf][3]);
                    mma_bf16(acc[mf][2 * nf],     ah[mf], bl[nf][0], bl[nf][2]);
                    mma_bf16(acc[mf][2 * nf + 1], ah[mf], bl[nf][1], bl[nf][3]);
                    mma_bf16(acc[mf][2 * nf],     al[mf], bh[nf][0], bh[nf][2]);
                    mma_bf16(acc[mf][2 * nf + 1], al[mf], bh[nf][1], bh[nf][3]);
                }
            }
        }
        __syncthreads();
    }

    const int erow = m0 + wm * 64 + (lane >> 2);
    const int ecol = n0 + wn * 32 + (lane & 3) * 2;
#pragma unroll
    for (int mf = 0; mf < 4; mf++) {
#pragma unroll
        for (int nf = 0; nf < 4; nf++) {
            if (MODE == 0) {
                float* p0 = Cf + (size_t)(erow + mf * 16) * DM + ecol + nf * 8;
                float* p1 = p0 + 8 * DM;
                *(float2*)p0 = make_float2(acc[mf][nf][0], acc[mf][nf][1]);
                *(float2*)p1 = make_float2(acc[mf][nf][2], acc[mf][nf][3]);
            } else {
                uint32_t h2, l2;
                size_t o0 = (size_t)(erow + mf * 16) * DM + ecol + nf * 8;
                split2(acc[mf][nf][0], acc[mf][nf][1], h2, l2);
                *(uint32_t*)(Chi + o0) = h2;
                *(uint32_t*)(Clo + o0) = l2;
                split2(acc[mf][nf][2], acc[mf][nf][3], h2, l2);
                *(uint32_t*)(Chi + o0 + 8 * DM) = h2;
                *(uint32_t*)(Clo + o0 + 8 * DM) = l2;
            }
        }
    }
}

// =================================================================
// fp32 -> (bf16 hi, bf16 lo) split (for x and W inputs)
// =================================================================
__global__ void __launch_bounds__(256)
split_bf16(const float* __restrict__ in, __nv_bfloat16* __restrict__ hi,
           __nv_bfloat16* __restrict__ lo, int n4)
{
    int i = blockIdx.x * blockDim.x + threadIdx.x;
    if (i >= n4) return;
    float4 x = ((const float4*)in)[i];
    uint32_t h0, l0, h1, l1;
    split2(x.x, x.y, h0, l0);
    split2(x.z, x.w, h1, l1);
    ((uint32_t*)hi)[2 * i]     = h0;
    ((uint32_t*)hi)[2 * i + 1] = h1;
    ((uint32_t*)lo)[2 * i]     = l0;
    ((uint32_t*)lo)[2 * i + 1] = l1;
}

// =================================================================
// FlashAttention-2 style causal ALiBi attention, split-bf16 HMMA.
// Q/K/V/O layout: (B*T, DM) with head h at cols h*64..h*64+63.
// CTA: 128 q rows, 8 warps (16 rows each), K blocks of 64.
// smem: Qhi/Qlo (2x16KB) + double-buffered Khi/Klo/Vhi/Vlo (2x32KB) = 96KB.
// =================================================================
#define AT_Q 128
#define AT_K 64
#define ATT_SMEM (32768 + 65536)

__device__ __forceinline__ void load_kv(uint32_t base,
        const __nv_bfloat16* khi, const __nv_bfloat16* klo,
        const __nv_bfloat16* vhi, const __nv_bfloat16* vlo,
        int b, int h, int kb, int tid)
{
    size_t grow = (size_t)(b * T_ + kb * AT_K) * DM + h * HD;
#pragma unroll
    for (int t = 0; t < 2; t++) {
        int idx = tid + t * 256;         // 512 -> 64 rows x 8 chunks
        int r = idx >> 3;
        int c = idx & 7;
        uint32_t sw = swz(r, c);
        size_t off = grow + (size_t)r * DM;
        cp16(base +         sw, (const char*)(khi + off) + c * 16);
        cp16(base +  8192 + sw, (const char*)(klo + off) + c * 16);
        cp16(base + 16384 + sw, (const char*)(vhi + off) + c * 16);
        cp16(base + 24576 + sw, (const char*)(vlo + off) + c * 16);
    }
}

__global__ void __launch_bounds__(256)
attn_mma(const __nv_bfloat16* __restrict__ qhi, const __nv_bfloat16* __restrict__ qlo,
         const __nv_bfloat16* __restrict__ khi, const __nv_bfloat16* __restrict__ klo,
         const __nv_bfloat16* __restrict__ vhi, const __nv_bfloat16* __restrict__ vlo,
         __nv_bfloat16* __restrict__ ohi, __nv_bfloat16* __restrict__ olo)
{
    extern __shared__ char smraw[];
    const uint32_t sb = smem_u32(smraw);
    const int tid = threadIdx.x, w = tid >> 5, lane = tid & 31;
    const int h = blockIdx.y, b = blockIdx.z;
    const int i0 = (gridDim.x - 1 - blockIdx.x) * AT_Q;   // heavy tiles first
    const int lrow = lane & 15, lsel = lane >> 4;
    const int rq = lane >> 2, c2 = (lane & 3) * 2;
    const int irow_base = i0 + w * 16;
    const int irow = irow_base + rq;

    const float slope  = ex2(-0.5f * (float)(h + 1));
    const float slope2 = slope * 1.4426950408889634f;     // slope*log2(e)
    const float scale2 = 0.18033688011112042f;            // 0.125*log2(e)

    const uint32_t sQh = sb, sQl = sb + 16384;
    auto stgK = [&](int s) { return sb + 32768 + s * 32768; };

    // prologue: Q tile (hi+lo) + KV block 0
    {
        const char* gqh = (const char*)(qhi + (size_t)(b * T_ + i0) * DM + h * HD);
        const char* gql = (const char*)(qlo + (size_t)(b * T_ + i0) * DM + h * HD);
#pragma unroll
        for (int t = 0; t < 4; t++) {
            int idx = tid + t * 256;     // 1024 -> 128 rows x 8 chunks
            int r = idx >> 3;
            int c = idx & 7;
            uint32_t sw = swz(r, c);
            cp16(sQh + sw, gqh + (size_t)r * DM * 2 + c * 16);
            cp16(sQl + sw, gql + (size_t)r * DM * 2 + c * 16);
        }
        load_kv(stgK(0), khi, klo, vhi, vlo, b, h, 0, tid);
        CP_COMMIT();
    }

    uint32_t qh[4][4], ql[4][4];
    float O[8][4];
#pragma unroll
    for (int i = 0; i < 8; i++)
#pragma unroll
        for (int e = 0; e < 4; e++) O[i][e] = 0.f;
    float m0 = -1e30f, m1 = -1e30f, l0 = 0.f, l1 = 0.f;

    const int NB = (i0 + AT_Q) / AT_K;

    for (int kb = 0; kb < NB; kb++) {
        int s = kb & 1;
        if (kb + 1 < NB) {
            load_kv(stgK(s ^ 1), khi, klo, vhi, vlo, b, h, kb + 1, tid);
            CP_COMMIT();
            asm volatile("cp.async.wait_group 1;");
        } else {
            asm volatile("cp.async.wait_group 0;");
        }
        __syncthreads();

        if (kb == 0) {   // Q frags -> registers (once)
#pragma unroll
            for (int ks = 0; ks < 4; ks++) {
                int r = w * 16 + lrow;
                uint32_t off = (uint32_t)(r * 128 + (((2 * ks + lsel) ^ (r & 7)) << 4));
                ldsm4(qh[ks], sQh + off);
                ldsm4(ql[ks], sQl + off);
            }
        }

        // skip blocks fully above the causal diagonal for this warp
        if (kb * AT_K <= irow_base + 15) {
            const uint32_t sKh = stgK(s), sKl = sKh + 8192;
            const uint32_t sVh = sKh + 16384, sVl = sKh + 24576;

            float S[8][4];
#pragma unroll
            for (int i = 0; i < 8; i++)
#pragma unroll
                for (int e = 0; e < 4; e++) S[i][e] = 0.f;

            // ---- S = (Qhi+Qlo)(Khi+Klo)^T  (3 passes)
#pragma unroll
            for (int ks = 0; ks < 4; ks++) {
#pragma unroll
                for (int np = 0; np < 4; np++) {
                    int r = np * 16 + lrow;
                    uint32_t off = (uint32_t)(r * 128 + (((2 * ks + lsel) ^ (r & 7)) << 4));
                    uint32_t bh[4], bl[4];
                    ldsm4(bh, sKh + off);
                    ldsm4(bl, sKl + off);
                    mma_bf16(S[2 * np],     qh[ks], bh[0], bh[2]);
                    mma_bf16(S[2 * np + 1], qh[ks], bh[1], bh[3]);
                    mma_bf16(S[2 * np],     qh[ks], bl[0], bl[2]);
                    mma_bf16(S[2 * np + 1], qh[ks], bl[1], bl[3]);
                    mma_bf16(S[2 * np],     ql[ks], bh[0], bh[2]);
                    mma_bf16(S[2 * np + 1], ql[ks], bh[1], bh[3]);
                }
            }

            // ---- ALiBi bias + causal mask + online softmax (log2 domain)
            const int jb = kb * AT_K + c2;
            const bool nomask = (kb * AT_K + 63) <= irow_base;
            float rm0 = -1e30f, rm1 = -1e30f;
#pragma unroll
            for (int nf = 0; nf < 8; nf++) {
                int d0 = irow - (jb + 8 * nf);
                float fd = (float)d0;
                float bia = -slope2 * fd;
                float t0 = fmaf(S[nf][0], scale2, bia);
                float t1 = fmaf(S[nf][1], scale2, bia + slope2);
                float t2 = fmaf(S[nf][2], scale2, bia - 8.f * slope2);
                float t3 = fmaf(S[nf][3], scale2, bia - 7.f * slope2);
                if (!nomask) {
                    t0 = (d0 >= 0)  ? t0 : -1e30f;
                    t1 = (d0 >= 1)  ? t1 : -1e30f;
                    t2 = (d0 >= -8) ? t2 : -1e30f;
                    t3 = (d0 >= -7) ? t3 : -1e30f;
                }
                S[nf][0] = t0; S[nf][1] = t1; S[nf][2] = t2; S[nf][3] = t3;
                rm0 = fmaxf(rm0, fmaxf(t0, t1));
                rm1 = fmaxf(rm1, fmaxf(t2, t3));
            }
            rm0 = fmaxf(rm0, __shfl_xor_sync(0xffffffffu, rm0, 1));
            rm0 = fmaxf(rm0, __shfl_xor_sync(0xffffffffu, rm0, 2));
            rm1 = fmaxf(rm1, __shfl_xor_sync(0xffffffffu, rm1, 1));
            rm1 = fmaxf(rm1, __shfl_xor_sync(0xffffffffu, rm1, 2));

            float m0n = fmaxf(m0, rm0), m1n = fmaxf(m1, rm1);
            float cr0 = ex2(m0 - m0n), cr1 = ex2(m1 - m1n);
            m0 = m0n; m1 = m1n;
            l0 *= cr0; l1 *= cr1;
#pragma unroll
            for (int nf = 0; nf < 8; nf++) {
                O[nf][0] *= cr0; O[nf][1] *= cr0;
                O[nf][2] *= cr1; O[nf][3] *= cr1;
            }
#pragma unroll
            for (int nf = 0; nf < 8; nf++) {
                float p0 = ex2(S[nf][0] - m0);
                float p1 = ex2(S[nf][1] - m0);
                float p2 = ex2(S[nf][2] - m1);
                float p3 = ex2(S[nf][3] - m1);
                S[nf][0] = p0; S[nf][1] = p1; S[nf][2] = p2; S[nf][3] = p3;
                l0 += p0 + p1;
                l1 += p2 + p3;
            }

            // ---- O += (Phi+Plo)(Vhi+Vlo)  (3 passes)
#pragma unroll
            for (int ks2 = 0; ks2 < 4; ks2++) {
                uint32_t ah[4], al[4];
                split2(S[2 * ks2][0],     S[2 * ks2][1],     ah[0], al[0]);
                split2(S[2 * ks2][2],     S[2 * ks2][3],     ah[1], al[1]);
                split2(S[2 * ks2 + 1][0], S[2 * ks2 + 1][1], ah[2], al[2]);
                split2(S[2 * ks2 + 1][2], S[2 * ks2 + 1][3], ah[3], al[3]);
#pragma unroll
                for (int nf2 = 0; nf2 < 4; nf2++) {
                    int r = ks2 * 16 + lrow;
                    uint32_t off = (uint32_t)(r * 128 + (((2 * nf2 + lsel) ^ (r & 7)) << 4));
                    uint32_t bh[4], bl[4];
                    ldsm4t(bh, sVh + off);
                    ldsm4t(bl, sVl + off);
                    mma_bf16(O[2 * nf2],     ah, bh[0], bh[1]);
                    mma_bf16(O[2 * nf2 + 1], ah, bh[2], bh[3]);
                    mma_bf16(O[2 * nf2],     ah, bl[0], bl[1]);
                    mma_bf16(O[2 * nf2 + 1], ah, bl[2], bl[3]);
                    mma_bf16(O[2 * nf2],     al, bh[0], bh[1]);
                    mma_bf16(O[2 * nf2 + 1], al, bh[2], bh[3]);
                }
            }
        }
        __syncthreads();
    }

    // finalize: complete row sums across the quad, normalize, split-store
    l0 += __shfl_xor_sync(0xffffffffu, l0, 1);
    l0 += __shfl_xor_sync(0xffffffffu, l0, 2);
    l1 += __shfl_xor_sync(0xffffffffu, l1, 1);
    l1 += __shfl_xor_sync(0xffffffffu, l1, 2);
    float iv0 = 1.0f / l0, iv1 = 1.0f / l1;

    size_t obase = (size_t)(b * T_ + irow) * DM + h * HD + c2;
#pragma unroll
    for (int nf = 0; nf < 8; nf++) {
        uint32_t h2, l2;
        split2(O[nf][0] * iv0, O[nf][1] * iv0, h2, l2);
        *(uint32_t*)(ohi + obase + 8 * nf) = h2;
        *(uint32_t*)(olo + obase + 8 * nf) = l2;
        split2(O[nf][2] * iv1, O[nf][3] * iv1, h2, l2);
        *(uint32_t*)(ohi + obase + 8 * DM + 8 * nf) = h2;
        *(uint32_t*)(olo + obase + 8 * DM + 8 * nf) = l2;
    }
}

// =================================================================
extern "C" void kernel_launch(void* const* d_in, const int* in_sizes, int n_in,
                              void* d_out, int out_size)
{
    const float* x  = (const float*)d_in[0];
    const float* Wq = (const float*)d_in[1];
    const float* Wk = (const float*)d_in[2];
    const float* Wv = (const float*)d_in[3];
    const float* Wo = (const float*)d_in[4];
    float* out = (float*)d_out;

    __nv_bfloat16 *xhi, *xlo, *whi, *wlo;
    __nv_bfloat16 *qhi, *qlo, *khi, *klo, *vhi, *vlo, *ahi, *alo;
    cudaGetSymbolAddress((void**)&xhi, g_xhi);
    cudaGetSymbolAddress((void**)&xlo, g_xlo);
    cudaGetSymbolAddress((void**)&whi, g_whi);
    cudaGetSymbolAddress((void**)&wlo, g_wlo);
    cudaGetSymbolAddress((void**)&qhi, g_qhi);
    cudaGetSymbolAddress((void**)&qlo, g_qlo);
    cudaGetSymbolAddress((void**)&khi, g_khi);
    cudaGetSymbolAddress((void**)&klo, g_klo);
    cudaGetSymbolAddress((void**)&vhi, g_vhi);
    cudaGetSymbolAddress((void**)&vlo, g_vlo);
    cudaGetSymbolAddress((void**)&ahi, g_ohi);
    cudaGetSymbolAddress((void**)&alo, g_olo);

    cudaFuncSetAttribute(mma_split_gemm<0>,
                         cudaFuncAttributeMaxDynamicSharedMemorySize, GEMM_SMEM);
    cudaFuncSetAttribute(mma_split_gemm<1>,
                         cudaFuncAttributeMaxDynamicSharedMemorySize, GEMM_SMEM);
    cudaFuncSetAttribute(attn_mma,
                         cudaFuncAttributeMaxDynamicSharedMemorySize, ATT_SMEM);

    const int nx4 = ROWS * DM / 4;
    const int nw4 = DM * DM / 4;
    dim3 ggrid(DM / 128, ROWS / 128);   // (8, 32)

    split_bf16<<<(nx4 + 255) / 256, 256>>>(x, xhi, xlo, nx4);

    split_bf16<<<(nw4 + 255) / 256, 256>>>(Wq, whi, wlo, nw4);
    mma_split_gemm<1><<<ggrid, 256, GEMM_SMEM>>>(xhi, xlo, whi, wlo, nullptr, qhi, qlo);
    split_bf16<<<(nw4 + 255) / 256, 256>>>(Wk, whi, wlo, nw4);
    mma_split_gemm<1><<<ggrid, 256, GEMM_SMEM>>>(xhi, xlo, whi, wlo, nullptr, khi, klo);
    split_bf16<<<(nw4 + 255) / 256, 256>>>(Wv, whi, wlo, nw4);
    mma_split_gemm<1><<<ggrid, 256, GEMM_SMEM>>>(xhi, xlo, whi, wlo, nullptr, vhi, vlo);

    dim3 agrid(T_ / AT_Q, H_, B_);      // (16, 16, 2)
    attn_mma<<<agrid, 256, ATT_SMEM>>>(qhi, qlo, khi, klo, vhi, vlo, ahi, alo);

    split_bf16<<<(nw4 + 255) / 256, 256>>>(Wo, whi, wlo, nw4);
    mma_split_gemm<0><<<ggrid, 256, GEMM_SMEM>>>(ahi, alo, whi, wlo, out, nullptr, nullptr);
}

// round 7
// speedup vs baseline: 14.1023x; 2.4149x over previous
#include <cuda_runtime.h>
#include <cuda_fp16.h>
#include <cstdint>

#define B_   2
#define T_   2048
#define DM   1024
#define H_   16
#define HD   64
#define ROWS (B_ * T_)        // 4096

// ---------------- scratch (no cudaMalloc allowed) ----------------
__device__ __half g_xh[ROWS * DM];
__device__ __half g_wh[4 * DM * DM];   // Wq, Wk, Wv, Wo (fp16)
__device__ __half g_qh[ROWS * DM];
__device__ __half g_kh[ROWS * DM];
__device__ __half g_vh[ROWS * DM];
__device__ __half g_ah[ROWS * DM];

// =================================================================
// low-level helpers
// =================================================================
__device__ __forceinline__ uint32_t smem_u32(const void* p) {
    uint32_t a;
    asm("{ .reg .u64 t; cvta.to.shared.u64 t, %1; cvt.u32.u64 %0, t; }"
        : "=r"(a) : "l"(p));
    return a;
}
__device__ __forceinline__ void cp16(uint32_t dst, const void* src) {
    asm volatile("cp.async.cg.shared.global [%0], [%1], 16;" :: "r"(dst), "l"(src));
}
#define CP_COMMIT() asm volatile("cp.async.commit_group;")

__device__ __forceinline__ void ldsm4(uint32_t (&r)[4], uint32_t addr) {
    asm volatile("ldmatrix.sync.aligned.m8n8.x4.shared.b16 {%0,%1,%2,%3}, [%4];"
                 : "=r"(r[0]), "=r"(r[1]), "=r"(r[2]), "=r"(r[3]) : "r"(addr));
}
__device__ __forceinline__ void ldsm4t(uint32_t (&r)[4], uint32_t addr) {
    asm volatile("ldmatrix.sync.aligned.m8n8.x4.trans.shared.b16 {%0,%1,%2,%3}, [%4];"
                 : "=r"(r[0]), "=r"(r[1]), "=r"(r[2]), "=r"(r[3]) : "r"(addr));
}
__device__ __forceinline__ void mma_f16(float (&d)[4], const uint32_t (&a)[4],
                                        uint32_t b0, uint32_t b1) {
    asm volatile(
        "mma.sync.aligned.m16n8k16.row.col.f32.f16.f16.f32 "
        "{%0,%1,%2,%3}, {%4,%5,%6,%7}, {%8,%9}, {%0,%1,%2,%3};"
        : "+f"(d[0]), "+f"(d[1]), "+f"(d[2]), "+f"(d[3])
        : "r"(a[0]), "r"(a[1]), "r"(a[2]), "r"(a[3]), "r"(b0), "r"(b1));
}
__device__ __forceinline__ float ex2(float x) {
    float y;
    asm("ex2.approx.ftz.f32 %0, %1;" : "=f"(y) : "f"(x));
    return y;
}
// pack two fp32 -> fp16x2 (low = c0, high = c1)
__device__ __forceinline__ uint32_t h2pack(float c0, float c1) {
    uint32_t r;
    asm("cvt.rn.f16x2.f32 %0, %1, %2;" : "=r"(r) : "f"(c1), "f"(c0));
    return r;
}
// swizzled offset inside a 128B-row tile (r = row, c = 16B chunk 0..7)
__device__ __forceinline__ uint32_t swz(int r, int c) {
    return (uint32_t)(r * 128 + ((c ^ (r & 7)) << 4));
}

// =================================================================
// fp32 -> fp16 converts
// =================================================================
__global__ void __launch_bounds__(256)
conv_x(const float* __restrict__ in, __half* __restrict__ out, int n4)
{
    int i = blockIdx.x * blockDim.x + threadIdx.x;
    if (i >= n4) return;
    float4 x = ((const float4*)in)[i];
    uint2 o;
    o.x = h2pack(x.x, x.y);
    o.y = h2pack(x.z, x.w);
    ((uint2*)out)[i] = o;
}
__global__ void __launch_bounds__(256)
conv_w(const float* __restrict__ w0, const float* __restrict__ w1,
       const float* __restrict__ w2, const float* __restrict__ w3,
       __half* __restrict__ out)
{
    const float* src = (blockIdx.y == 0) ? w0 : (blockIdx.y == 1) ? w1
                     : (blockIdx.y == 2) ? w2 : w3;
    __half* dst = out + (size_t)blockIdx.y * DM * DM;
    int i = blockIdx.x * blockDim.x + threadIdx.x;
    float4 x = ((const float4*)src)[i];
    uint2 o;
    o.x = h2pack(x.x, x.y);
    o.y = h2pack(x.z, x.w);
    ((uint2*)dst)[i] = o;
}

// =================================================================
// fp16 HMMA GEMM: C[4096,1024] = A @ W^T (both row-major, K contig).
// CTA 128x128, 8 warps m64n32, BK=64, double-buffered cp.async.
// MODE 0: fp32 C.  MODE 1: fp16 C.
// =================================================================
#define GBK      64
#define NKC      (DM / GBK)     // 16
#define TILE_B   (128 * 128)    // 16 KB per 128x64-fp16 tile
#define STAGE_B  (2 * TILE_B)   // A, W
#define GEMM_SMEM (2 * STAGE_B) // 64 KB

__device__ __forceinline__ void load_tile(uint32_t dst, const __half* g,
                                          int row0, int k0, int tid) {
    const char* gb = (const char*)(g + (size_t)row0 * DM + k0);
#pragma unroll
    for (int it = 0; it < 4; it++) {
        int idx = tid + it * 256;
        int r = idx >> 3;
        int c = idx & 7;
        cp16(dst + swz(r, c), gb + (size_t)r * DM * 2 + c * 16);
    }
}

template<int MODE>
__global__ void __launch_bounds__(256)
hgemm(const __half* __restrict__ A, const __half* __restrict__ W,
      float* __restrict__ Cf, __half* __restrict__ Ch)
{
    extern __shared__ char smraw[];
    const uint32_t sb = smem_u32(smraw);
    const int tid = threadIdx.x;
    const int wid = tid >> 5;
    const int lane = tid & 31;
    const int wm = wid >> 2;
    const int wn = wid & 3;
    const int n0 = blockIdx.x * 128;
    const int m0 = blockIdx.y * 128;

    const int lrow = lane & 15;
    const int lsel = lane >> 4;

    int arow[4], brow[2];
#pragma unroll
    for (int mf = 0; mf < 4; mf++) arow[mf] = wm * 64 + mf * 16 + lrow;
#pragma unroll
    for (int nf = 0; nf < 2; nf++) brow[nf] = wn * 32 + nf * 16 + lrow;

    float acc[4][4][4];
#pragma unroll
    for (int i = 0; i < 4; i++)
#pragma unroll
        for (int j = 0; j < 4; j++)
#pragma unroll
            for (int e = 0; e < 4; e++) acc[i][j][e] = 0.f;

    auto stage = [&](int s) { return sb + s * STAGE_B; };

    load_tile(stage(0) + 0 * TILE_B, A, m0, 0, tid);
    load_tile(stage(0) + 1 * TILE_B, W, n0, 0, tid);
    CP_COMMIT();

    for (int kc = 0; kc < NKC; kc++) {
        int s = kc & 1;
        if (kc + 1 < NKC) {
            int k0 = (kc + 1) * GBK;
            load_tile(stage(s ^ 1) + 0 * TILE_B, A, m0, k0, tid);
            load_tile(stage(s ^ 1) + 1 * TILE_B, W, n0, k0, tid);
            CP_COMMIT();
            asm volatile("cp.async.wait_group 1;");
        } else {
            asm volatile("cp.async.wait_group 0;");
        }
        __syncthreads();

        const uint32_t sA = stage(s) + 0 * TILE_B;
        const uint32_t sW = stage(s) + 1 * TILE_B;

#pragma unroll
        for (int t = 0; t < 4; t++) {
            const int c0 = t * 2;
            uint32_t ah[4][4];
#pragma unroll
            for (int mf = 0; mf < 4; mf++) {
                int r = arow[mf];
                uint32_t off = (uint32_t)(r * 128 + (((c0 + lsel) ^ (r & 7)) << 4));
                ldsm4(ah[mf], sA + off);
            }
            uint32_t bh[2][4];
#pragma unroll
            for (int nf = 0; nf < 2; nf++) {
                int r = brow[nf];
                uint32_t off = (uint32_t)(r * 128 + (((c0 + lsel) ^ (r & 7)) << 4));
                ldsm4(bh[nf], sW + off);
            }
#pragma unroll
            for (int mf = 0; mf < 4; mf++) {
#pragma unroll
                for (int nf = 0; nf < 2; nf++) {
                    mma_f16(acc[mf][2 * nf],     ah[mf], bh[nf][0], bh[nf][2]);
                    mma_f16(acc[mf][2 * nf + 1], ah[mf], bh[nf][1], bh[nf][3]);
                }
            }
        }
        __syncthreads();
    }

    const int erow = m0 + wm * 64 + (lane >> 2);
    const int ecol = n0 + wn * 32 + (lane & 3) * 2;
#pragma unroll
    for (int mf = 0; mf < 4; mf++) {
#pragma unroll
        for (int nf = 0; nf < 4; nf++) {
            size_t o0 = (size_t)(erow + mf * 16) * DM + ecol + nf * 8;
            if (MODE == 0) {
                *(float2*)(Cf + o0) = make_float2(acc[mf][nf][0], acc[mf][nf][1]);
                *(float2*)(Cf + o0 + 8 * DM) = make_float2(acc[mf][nf][2], acc[mf][nf][3]);
            } else {
                *(uint32_t*)(Ch + o0) = h2pack(acc[mf][nf][0], acc[mf][nf][1]);
                *(uint32_t*)(Ch + o0 + 8 * DM) = h2pack(acc[mf][nf][2], acc[mf][nf][3]);
            }
        }
    }
}

// =================================================================
// FlashAttention-2 style causal ALiBi attention, fp16 HMMA, 1-pass.
// Layout: (B*T, DM), head h at cols h*64..h*64+63.
// CTA: 128 q rows, 8 warps (16 rows each), K blocks of 64.
// smem: Q 16KB + 2 stages x (K 8KB + V 8KB) = 48KB.
// =================================================================
#define AT_Q 128
#define AT_K 64
#define ATT_SMEM (16384 + 32768)

__device__ __forceinline__ void load_kv(uint32_t base,
        const __half* kh, const __half* vh, int b, int h, int kb, int tid)
{
    size_t grow = (size_t)(b * T_ + kb * AT_K) * DM + h * HD;
#pragma unroll
    for (int t = 0; t < 2; t++) {
        int idx = tid + t * 256;         // 512 -> 64 rows x 8 chunks
        int r = idx >> 3;
        int c = idx & 7;
        uint32_t sw = swz(r, c);
        size_t off = grow + (size_t)r * DM;
        cp16(base +        sw, (const char*)(kh + off) + c * 16);
        cp16(base + 8192 + sw, (const char*)(vh + off) + c * 16);
    }
}

__global__ void __launch_bounds__(256)
attn_mma(const __half* __restrict__ qh, const __half* __restrict__ kh,
         const __half* __restrict__ vh, __half* __restrict__ oh)
{
    extern __shared__ char smraw[];
    const uint32_t sb = smem_u32(smraw);
    const int tid = threadIdx.x, w = tid >> 5, lane = tid & 31;
    const int h = blockIdx.y, b = blockIdx.z;
    const int i0 = (gridDim.x - 1 - blockIdx.x) * AT_Q;   // heavy tiles first
    const int lrow = lane & 15, lsel = lane >> 4;
    const int rq = lane >> 2, c2 = (lane & 3) * 2;
    const int irow_base = i0 + w * 16;
    const int irow = irow_base + rq;

    const float slope  = ex2(-0.5f * (float)(h + 1));
    const float slope2 = slope * 1.4426950408889634f;     // slope*log2(e)
    const float scale2 = 0.18033688011112042f;            // 0.125*log2(e)

    const uint32_t sQ = sb;
    auto stgK = [&](int s) { return sb + 16384 + s * 16384; };

    // prologue: Q tile + KV block 0
    {
        const char* gq = (const char*)(qh + (size_t)(b * T_ + i0) * DM + h * HD);
#pragma unroll
        for (int t = 0; t < 4; t++) {
            int idx = tid + t * 256;     // 1024 -> 128 rows x 8 chunks
            int r = idx >> 3;
            int c = idx & 7;
            cp16(sQ + swz(r, c), gq + (size_t)r * DM * 2 + c * 16);
        }
        load_kv(stgK(0), kh, vh, b, h, 0, tid);
        CP_COMMIT();
    }

    uint32_t qf[4][4];
    float O[8][4];
#pragma unroll
    for (int i = 0; i < 8; i++)
#pragma unroll
        for (int e = 0; e < 4; e++) O[i][e] = 0.f;
    float m0 = -1e30f, m1 = -1e30f, l0 = 0.f, l1 = 0.f;

    const int NB = (i0 + AT_Q) / AT_K;

    for (int kb = 0; kb < NB; kb++) {
        int s = kb & 1;
        if (kb + 1 < NB) {
            load_kv(stgK(s ^ 1), kh, vh, b, h, kb + 1, tid);
            CP_COMMIT();
            asm volatile("cp.async.wait_group 1;");
        } else {
            asm volatile("cp.async.wait_group 0;");
        }
        __syncthreads();

        if (kb == 0) {   // Q frags -> registers (once)
#pragma unroll
            for (int ks = 0; ks < 4; ks++) {
                int r = w * 16 + lrow;
                uint32_t off = (uint32_t)(r * 128 + (((2 * ks + lsel) ^ (r & 7)) << 4));
                ldsm4(qf[ks], sQ + off);
            }
        }

        // skip blocks fully above the causal diagonal for this warp
        if (kb * AT_K <= irow_base + 15) {
            const uint32_t sK = stgK(s), sV = sK + 8192;

            float S[8][4];
#pragma unroll
            for (int i = 0; i < 8; i++)
#pragma unroll
                for (int e = 0; e < 4; e++) S[i][e] = 0.f;

            // ---- S = Q K^T (single fp16 pass)
#pragma unroll
            for (int ks = 0; ks < 4; ks++) {
#pragma unroll
                for (int np = 0; np < 4; np++) {
                    int r = np * 16 + lrow;
                    uint32_t off = (uint32_t)(r * 128 + (((2 * ks + lsel) ^ (r & 7)) << 4));
                    uint32_t bh[4];
                    ldsm4(bh, sK + off);
                    mma_f16(S[2 * np],     qf[ks], bh[0], bh[2]);
                    mma_f16(S[2 * np + 1], qf[ks], bh[1], bh[3]);
                }
            }

            // ---- ALiBi bias + causal mask + online softmax (log2 domain)
            const int jb = kb * AT_K + c2;
            const bool nomask = (kb * AT_K + 63) <= irow_base;
            float rm0 = -1e30f, rm1 = -1e30f;
#pragma unroll
            for (int nf = 0; nf < 8; nf++) {
                int d0 = irow - (jb + 8 * nf);
                float fd = (float)d0;
                float bia = -slope2 * fd;
                float t0 = fmaf(S[nf][0], scale2, bia);
                float t1 = fmaf(S[nf][1], scale2, bia + slope2);
                float t2 = fmaf(S[nf][2], scale2, bia - 8.f * slope2);
                float t3 = fmaf(S[nf][3], scale2, bia - 7.f * slope2);
                if (!nomask) {
                    t0 = (d0 >= 0)  ? t0 : -1e30f;
                    t1 = (d0 >= 1)  ? t1 : -1e30f;
                    t2 = (d0 >= -8) ? t2 : -1e30f;
                    t3 = (d0 >= -7) ? t3 : -1e30f;
                }
                S[nf][0] = t0; S[nf][1] = t1; S[nf][2] = t2; S[nf][3] = t3;
                rm0 = fmaxf(rm0, fmaxf(t0, t1));
                rm1 = fmaxf(rm1, fmaxf(t2, t3));
            }
            rm0 = fmaxf(rm0, __shfl_xor_sync(0xffffffffu, rm0, 1));
            rm0 = fmaxf(rm0, __shfl_xor_sync(0xffffffffu, rm0, 2));
            rm1 = fmaxf(rm1, __shfl_xor_sync(0xffffffffu, rm1, 1));
            rm1 = fmaxf(rm1, __shfl_xor_sync(0xffffffffu, rm1, 2));

            float m0n = fmaxf(m0, rm0), m1n = fmaxf(m1, rm1);
            float cr0 = ex2(m0 - m0n), cr1 = ex2(m1 - m1n);
            m0 = m0n; m1 = m1n;
            l0 *= cr0; l1 *= cr1;
#pragma unroll
            for (int nf = 0; nf < 8; nf++) {
                O[nf][0] *= cr0; O[nf][1] *= cr0;
                O[nf][2] *= cr1; O[nf][3] *= cr1;
            }
#pragma unroll
            for (int nf = 0; nf < 8; nf++) {
                float p0 = ex2(S[nf][0] - m0);
                float p1 = ex2(S[nf][1] - m0);
                float p2 = ex2(S[nf][2] - m1);
                float p3 = ex2(S[nf][3] - m1);
                S[nf][0] = p0; S[nf][1] = p1; S[nf][2] = p2; S[nf][3] = p3;
                l0 += p0 + p1;
                l1 += p2 + p3;
            }

            // ---- O += P V (single fp16 pass)
#pragma unroll
            for (int ks2 = 0; ks2 < 4; ks2++) {
                uint32_t af[4];
                af[0] = h2pack(S[2 * ks2][0],     S[2 * ks2][1]);
                af[1] = h2pack(S[2 * ks2][2],     S[2 * ks2][3]);
                af[2] = h2pack(S[2 * ks2 + 1][0], S[2 * ks2 + 1][1]);
                af[3] = h2pack(S[2 * ks2 + 1][2], S[2 * ks2 + 1][3]);
#pragma unroll
                for (int nf2 = 0; nf2 < 4; nf2++) {
                    int r = ks2 * 16 + lrow;
                    uint32_t off = (uint32_t)(r * 128 + (((2 * nf2 + lsel) ^ (r & 7)) << 4));
                    uint32_t bh[4];
                    ldsm4t(bh, sV + off);
                    mma_f16(O[2 * nf2],     af, bh[0], bh[1]);
                    mma_f16(O[2 * nf2 + 1], af, bh[2], bh[3]);
                }
            }
        }
        __syncthreads();
    }

    // finalize: complete row sums across the quad, normalize, store fp16
    l0 += __shfl_xor_sync(0xffffffffu, l0, 1);
    l0 += __shfl_xor_sync(0xffffffffu, l0, 2);
    l1 += __shfl_xor_sync(0xffffffffu, l1, 1);
    l1 += __shfl_xor_sync(0xffffffffu, l1, 2);
    float iv0 = 1.0f / l0, iv1 = 1.0f / l1;

    size_t obase = (size_t)(b * T_ + irow) * DM + h * HD + c2;
#pragma unroll
    for (int nf = 0; nf < 8; nf++) {
        *(uint32_t*)(oh + obase + 8 * nf) =
            h2pack(O[nf][0] * iv0, O[nf][1] * iv0);
        *(uint32_t*)(oh + obase + 8 * DM + 8 * nf) =
            h2pack(O[nf][2] * iv1, O[nf][3] * iv1);
    }
}

// =================================================================
extern "C" void kernel_launch(void* const* d_in, const int* in_sizes, int n_in,
                              void* d_out, int out_size)
{
    const float* x  = (const float*)d_in[0];
    const float* Wq = (const float*)d_in[1];
    const float* Wk = (const float*)d_in[2];
    const float* Wv = (const float*)d_in[3];
    const float* Wo = (const float*)d_in[4];
    float* out = (float*)d_out;

    __half *xh, *wh, *qh, *kh, *vh, *ah;
    cudaGetSymbolAddress((void**)&xh, g_xh);
    cudaGetSymbolAddress((void**)&wh, g_wh);
    cudaGetSymbolAddress((void**)&qh, g_qh);
    cudaGetSymbolAddress((void**)&kh, g_kh);
    cudaGetSymbolAddress((void**)&vh, g_vh);
    cudaGetSymbolAddress((void**)&ah, g_ah);

    cudaFuncSetAttribute(hgemm<0>,
                         cudaFuncAttributeMaxDynamicSharedMemorySize, GEMM_SMEM);
    cudaFuncSetAttribute(hgemm<1>,
                         cudaFuncAttributeMaxDynamicSharedMemorySize, GEMM_SMEM);
    cudaFuncSetAttribute(attn_mma,
                         cudaFuncAttributeMaxDynamicSharedMemorySize, ATT_SMEM);

    const int nx4 = ROWS * DM / 4;
    const int nw4 = DM * DM / 4;
    dim3 ggrid(DM / 128, ROWS / 128);   // (8, 32)

    conv_x<<<(nx4 + 255) / 256, 256>>>(x, xh, nx4);
    conv_w<<<dim3(nw4 / 256, 4), 256>>>(Wq, Wk, Wv, Wo, wh);

    hgemm<1><<<ggrid, 256, GEMM_SMEM>>>(xh, wh + 0 * (size_t)DM * DM, nullptr, qh);
    hgemm<1><<<ggrid, 256, GEMM_SMEM>>>(xh, wh + 1 * (size_t)DM * DM, nullptr, kh);
    hgemm<1><<<ggrid, 256, GEMM_SMEM>>>(xh, wh + 2 * (size_t)DM * DM, nullptr, vh);

    dim3 agrid(T_ / AT_Q, H_, B_);      // (16, 16, 2)
    attn_mma<<<agrid, 256, ATT_SMEM>>>(qh, kh, vh, ah);

    hgemm<0><<<ggrid, 256, GEMM_SMEM>>>(ah, wh + 3 * (size_t)DM * DM, out, nullptr);
}

// round 8
// speedup vs baseline: 14.3847x; 1.0200x over previous
#include <cuda_runtime.h>
#include <cuda_fp16.h>
#include <cstdint>

#define B_   2
#define T_   2048
#define DM   1024
#define H_   16
#define HD   64
#define ROWS (B_ * T_)        // 4096

// ---------------- scratch (no cudaMalloc allowed) ----------------
__device__ __half g_xh[ROWS * DM];
__device__ __half g_wh[4 * DM * DM];   // Wq, Wk, Wv, Wo (fp16)
__device__ __half g_qh[ROWS * DM];
__device__ __half g_kh[ROWS * DM];
__device__ __half g_vh[ROWS * DM];
__device__ __half g_ah[ROWS * DM];

// =================================================================
// low-level helpers
// =================================================================
__device__ __forceinline__ uint32_t smem_u32(const void* p) {
    uint32_t a;
    asm("{ .reg .u64 t; cvta.to.shared.u64 t, %1; cvt.u32.u64 %0, t; }"
        : "=r"(a) : "l"(p));
    return a;
}
__device__ __forceinline__ void cp16(uint32_t dst, const void* src) {
    asm volatile("cp.async.cg.shared.global [%0], [%1], 16;" :: "r"(dst), "l"(src));
}
#define CP_COMMIT() asm volatile("cp.async.commit_group;")

__device__ __forceinline__ void ldsm4(uint32_t (&r)[4], uint32_t addr) {
    asm volatile("ldmatrix.sync.aligned.m8n8.x4.shared.b16 {%0,%1,%2,%3}, [%4];"
                 : "=r"(r[0]), "=r"(r[1]), "=r"(r[2]), "=r"(r[3]) : "r"(addr));
}
__device__ __forceinline__ void ldsm4t(uint32_t (&r)[4], uint32_t addr) {
    asm volatile("ldmatrix.sync.aligned.m8n8.x4.trans.shared.b16 {%0,%1,%2,%3}, [%4];"
                 : "=r"(r[0]), "=r"(r[1]), "=r"(r[2]), "=r"(r[3]) : "r"(addr));
}
__device__ __forceinline__ void mma_f16(float (&d)[4], const uint32_t (&a)[4],
                                        uint32_t b0, uint32_t b1) {
    asm volatile(
        "mma.sync.aligned.m16n8k16.row.col.f32.f16.f16.f32 "
        "{%0,%1,%2,%3}, {%4,%5,%6,%7}, {%8,%9}, {%0,%1,%2,%3};"
        : "+f"(d[0]), "+f"(d[1]), "+f"(d[2]), "+f"(d[3])
        : "r"(a[0]), "r"(a[1]), "r"(a[2]), "r"(a[3]), "r"(b0), "r"(b1));
}
__device__ __forceinline__ float ex2(float x) {
    float y;
    asm("ex2.approx.ftz.f32 %0, %1;" : "=f"(y) : "f"(x));
    return y;
}
__device__ __forceinline__ uint32_t h2pack(float c0, float c1) {
    uint32_t r;
    asm("cvt.rn.f16x2.f32 %0, %1, %2;" : "=r"(r) : "f"(c1), "f"(c0));
    return r;
}
__device__ __forceinline__ uint32_t swz(int r, int c) {
    return (uint32_t)(r * 128 + ((c ^ (r & 7)) << 4));
}

// =================================================================
// single fused fp32 -> fp16 convert: x (1M float4) + 4 W (256K each)
// =================================================================
#define NX4 (ROWS * DM / 4)   // 1048576
#define NW4 (DM * DM / 4)     // 262144

__global__ void __launch_bounds__(256)
conv_all(const float* __restrict__ x,
         const float* __restrict__ w0, const float* __restrict__ w1,
         const float* __restrict__ w2, const float* __restrict__ w3,
         __half* __restrict__ xh, __half* __restrict__ wh)
{
    int i = blockIdx.x * blockDim.x + threadIdx.x;
    const float* src;
    __half* dst;
    int off;
    if (i < NX4) {
        src = x; dst = xh; off = i;
    } else {
        int j = i - NX4;
        int w = j >> 18;              // / NW4
        off = j & (NW4 - 1);
        src = (w == 0) ? w0 : (w == 1) ? w1 : (w == 2) ? w2 : w3;
        dst = wh + (size_t)w * DM * DM;
    }
    float4 v = ((const float4*)src)[off];
    uint2 o;
    o.x = h2pack(v.x, v.y);
    o.y = h2pack(v.z, v.w);
    ((uint2*)dst)[off] = o;
}

// =================================================================
// fp16 HMMA GEMM body: CTA 128x128, 8 warps m64n32, BK=64,
// 3-stage cp.async pipeline (96 KB smem -> 2 CTAs/SM).
// =================================================================
#define GBK      64
#define NKC      (DM / GBK)     // 16
#define TILE_B   (128 * 128)    // 16 KB per 128x64-fp16 tile
#define STAGE_B  (2 * TILE_B)   // A tile + W tile
#define GEMM_SMEM (3 * STAGE_B) // 96 KB

__device__ __forceinline__ void load_tile(uint32_t dst, const __half* g,
                                          int row0, int k0, int tid) {
    const char* gb = (const char*)(g + (size_t)row0 * DM + k0);
#pragma unroll
    for (int it = 0; it < 4; it++) {
        int idx = tid + it * 256;
        int r = idx >> 3;
        int c = idx & 7;
        cp16(dst + swz(r, c), gb + (size_t)r * DM * 2 + c * 16);
    }
}

// MODE 0: fp32 C.  MODE 1: fp16 C.
template<int MODE>
__device__ __forceinline__ void hgemm_body(
    const __half* __restrict__ A, const __half* __restrict__ W,
    float* __restrict__ Cf, __half* __restrict__ Ch,
    int m0, int n0, uint32_t sb)
{
    const int tid = threadIdx.x;
    const int wid = tid >> 5;
    const int lane = tid & 31;
    const int wm = wid >> 2;
    const int wn = wid & 3;
    const int lrow = lane & 15;
    const int lsel = lane >> 4;

    int arow[4], brow[2];
#pragma unroll
    for (int mf = 0; mf < 4; mf++) arow[mf] = wm * 64 + mf * 16 + lrow;
#pragma unroll
    for (int nf = 0; nf < 2; nf++) brow[nf] = wn * 32 + nf * 16 + lrow;

    float acc[4][4][4];
#pragma unroll
    for (int i = 0; i < 4; i++)
#pragma unroll
        for (int j = 0; j < 4; j++)
#pragma unroll
            for (int e = 0; e < 4; e++) acc[i][j][e] = 0.f;

    auto stage = [&](int s) { return sb + s * STAGE_B; };

    // prologue: chunks 0,1 into stages 0,1
    load_tile(stage(0) + 0 * TILE_B, A, m0, 0, tid);
    load_tile(stage(0) + 1 * TILE_B, W, n0, 0, tid);
    CP_COMMIT();
    load_tile(stage(1) + 0 * TILE_B, A, m0, GBK, tid);
    load_tile(stage(1) + 1 * TILE_B, W, n0, GBK, tid);
    CP_COMMIT();

    for (int kc = 0; kc < NKC; kc++) {
        const int s = kc % 3;
        __syncthreads();   // protect stage (kc+2)%3 from overwrite
        if (kc + 2 < NKC) {
            int s2 = (kc + 2) % 3;
            int k0 = (kc + 2) * GBK;
            load_tile(stage(s2) + 0 * TILE_B, A, m0, k0, tid);
            load_tile(stage(s2) + 1 * TILE_B, W, n0, k0, tid);
            CP_COMMIT();
            asm volatile("cp.async.wait_group 2;");
        } else if (kc + 1 < NKC) {
            asm volatile("cp.async.wait_group 1;");
        } else {
            asm volatile("cp.async.wait_group 0;");
        }
        __syncthreads();

        const uint32_t sA = stage(s) + 0 * TILE_B;
        const uint32_t sW = stage(s) + 1 * TILE_B;

#pragma unroll
        for (int t = 0; t < 4; t++) {
            const int c0 = t * 2;
            uint32_t ah[4][4];
#pragma unroll
            for (int mf = 0; mf < 4; mf++) {
                int r = arow[mf];
                uint32_t off = (uint32_t)(r * 128 + (((c0 + lsel) ^ (r & 7)) << 4));
                ldsm4(ah[mf], sA + off);
            }
            uint32_t bh[2][4];
#pragma unroll
            for (int nf = 0; nf < 2; nf++) {
                int r = brow[nf];
                uint32_t off = (uint32_t)(r * 128 + (((c0 + lsel) ^ (r & 7)) << 4));
                ldsm4(bh[nf], sW + off);
            }
#pragma unroll
            for (int mf = 0; mf < 4; mf++) {
#pragma unroll
                for (int nf = 0; nf < 2; nf++) {
                    mma_f16(acc[mf][2 * nf],     ah[mf], bh[nf][0], bh[nf][2]);
                    mma_f16(acc[mf][2 * nf + 1], ah[mf], bh[nf][1], bh[nf][3]);
                }
            }
        }
    }

    const int erow = m0 + wm * 64 + (lane >> 2);
    const int ecol = n0 + wn * 32 + (lane & 3) * 2;
#pragma unroll
    for (int mf = 0; mf < 4; mf++) {
#pragma unroll
        for (int nf = 0; nf < 4; nf++) {
            size_t o0 = (size_t)(erow + mf * 16) * DM + ecol + nf * 8;
            if (MODE == 0) {
                *(float2*)(Cf + o0) = make_float2(acc[mf][nf][0], acc[mf][nf][1]);
                *(float2*)(Cf + o0 + 8 * DM) = make_float2(acc[mf][nf][2], acc[mf][nf][3]);
            } else {
                *(uint32_t*)(Ch + o0) = h2pack(acc[mf][nf][0], acc[mf][nf][1]);
                *(uint32_t*)(Ch + o0 + 8 * DM) = h2pack(acc[mf][nf][2], acc[mf][nf][3]);
            }
        }
    }
}

// fused QKV: grid (24, 32); blockIdx.x selects weight and N tile
__global__ void __launch_bounds__(256)
hgemm_qkv(const __half* __restrict__ A, const __half* __restrict__ Wall,
          __half* __restrict__ q, __half* __restrict__ k, __half* __restrict__ v)
{
    extern __shared__ char smraw[];
    const int wsel = blockIdx.x >> 3;
    const int n0 = (blockIdx.x & 7) * 128;
    const int m0 = blockIdx.y * 128;
    const __half* W = Wall + (size_t)wsel * DM * DM;
    __half* Ch = (wsel == 0) ? q : (wsel == 1) ? k : v;
    hgemm_body<1>(A, W, nullptr, Ch, m0, n0, smem_u32(smraw));
}

// output projection: grid (8, 32)
__global__ void __launch_bounds__(256)
hgemm_o(const __half* __restrict__ A, const __half* __restrict__ W,
        float* __restrict__ Cf)
{
    extern __shared__ char smraw[];
    hgemm_body<0>(A, W, Cf, nullptr, blockIdx.y * 128, blockIdx.x * 128,
                  smem_u32(smraw));
}

// =================================================================
// FlashAttention-2 style causal ALiBi attention, fp16 HMMA (as R7).
// =================================================================
#define AT_Q 128
#define AT_K 64
#define ATT_SMEM (16384 + 32768)

__device__ __forceinline__ void load_kv(uint32_t base,
        const __half* kh, const __half* vh, int b, int h, int kb, int tid)
{
    size_t grow = (size_t)(b * T_ + kb * AT_K) * DM + h * HD;
#pragma unroll
    for (int t = 0; t < 2; t++) {
        int idx = tid + t * 256;
        int r = idx >> 3;
        int c = idx & 7;
        uint32_t sw = swz(r, c);
        size_t off = grow + (size_t)r * DM;
        cp16(base +        sw, (const char*)(kh + off) + c * 16);
        cp16(base + 8192 + sw, (const char*)(vh + off) + c * 16);
    }
}

__global__ void __launch_bounds__(256)
attn_mma(const __half* __restrict__ qh, const __half* __restrict__ kh,
         const __half* __restrict__ vh, __half* __restrict__ oh)
{
    extern __shared__ char smraw[];
    const uint32_t sb = smem_u32(smraw);
    const int tid = threadIdx.x, w = tid >> 5, lane = tid & 31;
    const int h = blockIdx.y, b = blockIdx.z;
    const int i0 = (gridDim.x - 1 - blockIdx.x) * AT_Q;
    const int lrow = lane & 15, lsel = lane >> 4;
    const int rq = lane >> 2, c2 = (lane & 3) * 2;
    const int irow_base = i0 + w * 16;
    const int irow = irow_base + rq;

    const float slope  = ex2(-0.5f * (float)(h + 1));
    const float slope2 = slope * 1.4426950408889634f;
    const float scale2 = 0.18033688011112042f;

    const uint32_t sQ = sb;
    auto stgK = [&](int s) { return sb + 16384 + s * 16384; };

    {
        const char* gq = (const char*)(qh + (size_t)(b * T_ + i0) * DM + h * HD);
#pragma unroll
        for (int t = 0; t < 4; t++) {
            int idx = tid + t * 256;
            int r = idx >> 3;
            int c = idx & 7;
            cp16(sQ + swz(r, c), gq + (size_t)r * DM * 2 + c * 16);
        }
        load_kv(stgK(0), kh, vh, b, h, 0, tid);
        CP_COMMIT();
    }

    uint32_t qf[4][4];
    float O[8][4];
#pragma unroll
    for (int i = 0; i < 8; i++)
#pragma unroll
        for (int e = 0; e < 4; e++) O[i][e] = 0.f;
    float m0 = -1e30f, m1 = -1e30f, l0 = 0.f, l1 = 0.f;

    const int NB = (i0 + AT_Q) / AT_K;

    for (int kb = 0; kb < NB; kb++) {
        int s = kb & 1;
        if (kb + 1 < NB) {
            load_kv(stgK(s ^ 1), kh, vh, b, h, kb + 1, tid);
            CP_COMMIT();
            asm volatile("cp.async.wait_group 1;");
        } else {
            asm volatile("cp.async.wait_group 0;");
        }
        __syncthreads();

        if (kb == 0) {
#pragma unroll
            for (int ks = 0; ks < 4; ks++) {
                int r = w * 16 + lrow;
                uint32_t off = (uint32_t)(r * 128 + (((2 * ks + lsel) ^ (r & 7)) << 4));
                ldsm4(qf[ks], sQ + off);
            }
        }

        if (kb * AT_K <= irow_base + 15) {
            const uint32_t sK = stgK(s), sV = sK + 8192;

            float S[8][4];
#pragma unroll
            for (int i = 0; i < 8; i++)
#pragma unroll
                for (int e = 0; e < 4; e++) S[i][e] = 0.f;

#pragma unroll
            for (int ks = 0; ks < 4; ks++) {
#pragma unroll
                for (int np = 0; np < 4; np++) {
                    int r = np * 16 + lrow;
                    uint32_t off = (uint32_t)(r * 128 + (((2 * ks + lsel) ^ (r & 7)) << 4));
                    uint32_t bh[4];
                    ldsm4(bh, sK + off);
                    mma_f16(S[2 * np],     qf[ks], bh[0], bh[2]);
                    mma_f16(S[2 * np + 1], qf[ks], bh[1], bh[3]);
                }
            }

            const int jb = kb * AT_K + c2;
            const bool nomask = (kb * AT_K + 63) <= irow_base;
            float rm0 = -1e30f, rm1 = -1e30f;
#pragma unroll
            for (int nf = 0; nf < 8; nf++) {
                int d0 = irow - (jb + 8 * nf);
                float fd = (float)d0;
                float bia = -slope2 * fd;
                float t0 = fmaf(S[nf][0], scale2, bia);
                float t1 = fmaf(S[nf][1], scale2, bia + slope2);
                float t2 = fmaf(S[nf][2], scale2, bia - 8.f * slope2);
                float t3 = fmaf(S[nf][3], scale2, bia - 7.f * slope2);
                if (!nomask) {
                    t0 = (d0 >= 0)  ? t0 : -1e30f;
                    t1 = (d0 >= 1)  ? t1 : -1e30f;
                    t2 = (d0 >= -8) ? t2 : -1e30f;
                    t3 = (d0 >= -7) ? t3 : -1e30f;
                }
                S[nf][0] = t0; S[nf][1] = t1; S[nf][2] = t2; S[nf][3] = t3;
                rm0 = fmaxf(rm0, fmaxf(t0, t1));
                rm1 = fmaxf(rm1, fmaxf(t2, t3));
            }
            rm0 = fmaxf(rm0, __shfl_xor_sync(0xffffffffu, rm0, 1));
            rm0 = fmaxf(rm0, __shfl_xor_sync(0xffffffffu, rm0, 2));
            rm1 = fmaxf(rm1, __shfl_xor_sync(0xffffffffu, rm1, 1));
            rm1 = fmaxf(rm1, __shfl_xor_sync(0xffffffffu, rm1, 2));

            float m0n = fmaxf(m0, rm0), m1n = fmaxf(m1, rm1);
            float cr0 = ex2(m0 - m0n), cr1 = ex2(m1 - m1n);
            m0 = m0n; m1 = m1n;
            l0 *= cr0; l1 *= cr1;
#pragma unroll
            for (int nf = 0; nf < 8; nf++) {
                O[nf][0] *= cr0; O[nf][1] *= cr0;
                O[nf][2] *= cr1; O[nf][3] *= cr1;
            }
#pragma unroll
            for (int nf = 0; nf < 8; nf++) {
                float p0 = ex2(S[nf][0] - m0);
                float p1 = ex2(S[nf][1] - m0);
                float p2 = ex2(S[nf][2] - m1);
                float p3 = ex2(S[nf][3] - m1);
                S[nf][0] = p0; S[nf][1] = p1; S[nf][2] = p2; S[nf][3] = p3;
                l0 += p0 + p1;
                l1 += p2 + p3;
            }

#pragma unroll
            for (int ks2 = 0; ks2 < 4; ks2++) {
                uint32_t af[4];
                af[0] = h2pack(S[2 * ks2][0],     S[2 * ks2][1]);
                af[1] = h2pack(S[2 * ks2][2],     S[2 * ks2][3]);
                af[2] = h2pack(S[2 * ks2 + 1][0], S[2 * ks2 + 1][1]);
                af[3] = h2pack(S[2 * ks2 + 1][2], S[2 * ks2 + 1][3]);
#pragma unroll
                for (int nf2 = 0; nf2 < 4; nf2++) {
                    int r = ks2 * 16 + lrow;
                    uint32_t off = (uint32_t)(r * 128 + (((2 * nf2 + lsel) ^ (r & 7)) << 4));
                    uint32_t bh[4];
                    ldsm4t(bh, sV + off);
                    mma_f16(O[2 * nf2],     af, bh[0], bh[1]);
                    mma_f16(O[2 * nf2 + 1], af, bh[2], bh[3]);
                }
            }
        }
        __syncthreads();
    }

    l0 += __shfl_xor_sync(0xffffffffu, l0, 1);
    l0 += __shfl_xor_sync(0xffffffffu, l0, 2);
    l1 += __shfl_xor_sync(0xffffffffu, l1, 1);
    l1 += __shfl_xor_sync(0xffffffffu, l1, 2);
    float iv0 = 1.0f / l0, iv1 = 1.0f / l1;

    size_t obase = (size_t)(b * T_ + irow) * DM + h * HD + c2;
#pragma unroll
    for (int nf = 0; nf < 8; nf++) {
        *(uint32_t*)(oh + obase + 8 * nf) =
            h2pack(O[nf][0] * iv0, O[nf][1] * iv0);
        *(uint32_t*)(oh + obase + 8 * DM + 8 * nf) =
            h2pack(O[nf][2] * iv1, O[nf][3] * iv1);
    }
}

// =================================================================
extern "C" void kernel_launch(void* const* d_in, const int* in_sizes, int n_in,
                              void* d_out, int out_size)
{
    const float* x  = (const float*)d_in[0];
    const float* Wq = (const float*)d_in[1];
    const float* Wk = (const float*)d_in[2];
    const float* Wv = (const float*)d_in[3];
    const float* Wo = (const float*)d_in[4];
    float* out = (float*)d_out;

    __half *xh, *wh, *qh, *kh, *vh, *ah;
    cudaGetSymbolAddress((void**)&xh, g_xh);
    cudaGetSymbolAddress((void**)&wh, g_wh);
    cudaGetSymbolAddress((void**)&qh, g_qh);
    cudaGetSymbolAddress((void**)&kh, g_kh);
    cudaGetSymbolAddress((void**)&vh, g_vh);
    cudaGetSymbolAddress((void**)&ah, g_ah);

    cudaFuncSetAttribute(hgemm_qkv,
                         cudaFuncAttributeMaxDynamicSharedMemorySize, GEMM_SMEM);
    cudaFuncSetAttribute(hgemm_o,
                         cudaFuncAttributeMaxDynamicSharedMemorySize, GEMM_SMEM);
    cudaFuncSetAttribute(attn_mma,
                         cudaFuncAttributeMaxDynamicSharedMemorySize, ATT_SMEM);

    // fused converts: 1M (x) + 4x256K (W) float4 = 2M items / 256 = 8192 blocks
    conv_all<<<(NX4 + 4 * NW4) / 256, 256>>>(x, Wq, Wk, Wv, Wo, xh, wh);

    // fused QKV projections
    hgemm_qkv<<<dim3(24, ROWS / 128), 256, GEMM_SMEM>>>(xh, wh, qh, kh, vh);

    // attention
    dim3 agrid(T_ / AT_Q, H_, B_);      // (16, 16, 2)
    attn_mma<<<agrid, 256, ATT_SMEM>>>(qh, kh, vh, ah);

    // output projection
    hgemm_o<<<dim3(DM / 128, ROWS / 128), 256, GEMM_SMEM>>>(
        ah, wh + 3 * (size_t)DM * DM, out);
}

// round 9
// speedup vs baseline: 14.9252x; 1.0376x over previous
#include <cuda_runtime.h>
#include <cuda_fp16.h>
#include <cstdint>

#define B_   2
#define T_   2048
#define DM   1024
#define H_   16
#define HD   64
#define ROWS (B_ * T_)        // 4096

// ---------------- scratch (no cudaMalloc allowed) ----------------
__device__ __half g_xh[ROWS * DM];
__device__ __half g_wh[4 * DM * DM];   // Wq, Wk, Wv, Wo (fp16)
__device__ __half g_qh[ROWS * DM];
__device__ __half g_kh[ROWS * DM];
__device__ __half g_vh[ROWS * DM];
__device__ __half g_ah[ROWS * DM];

// =================================================================
// low-level helpers
// =================================================================
__device__ __forceinline__ uint32_t smem_u32(const void* p) {
    uint32_t a;
    asm("{ .reg .u64 t; cvta.to.shared.u64 t, %1; cvt.u32.u64 %0, t; }"
        : "=r"(a) : "l"(p));
    return a;
}
__device__ __forceinline__ void cp16(uint32_t dst, const void* src) {
    asm volatile("cp.async.cg.shared.global [%0], [%1], 16;" :: "r"(dst), "l"(src));
}
#define CP_COMMIT() asm volatile("cp.async.commit_group;")

__device__ __forceinline__ void ldsm4(uint32_t (&r)[4], uint32_t addr) {
    asm volatile("ldmatrix.sync.aligned.m8n8.x4.shared.b16 {%0,%1,%2,%3}, [%4];"
                 : "=r"(r[0]), "=r"(r[1]), "=r"(r[2]), "=r"(r[3]) : "r"(addr));
}
__device__ __forceinline__ void ldsm4t(uint32_t (&r)[4], uint32_t addr) {
    asm volatile("ldmatrix.sync.aligned.m8n8.x4.trans.shared.b16 {%0,%1,%2,%3}, [%4];"
                 : "=r"(r[0]), "=r"(r[1]), "=r"(r[2]), "=r"(r[3]) : "r"(addr));
}
__device__ __forceinline__ void mma_f16(float (&d)[4], const uint32_t (&a)[4],
                                        uint32_t b0, uint32_t b1) {
    asm volatile(
        "mma.sync.aligned.m16n8k16.row.col.f32.f16.f16.f32 "
        "{%0,%1,%2,%3}, {%4,%5,%6,%7}, {%8,%9}, {%0,%1,%2,%3};"
        : "+f"(d[0]), "+f"(d[1]), "+f"(d[2]), "+f"(d[3])
        : "r"(a[0]), "r"(a[1]), "r"(a[2]), "r"(a[3]), "r"(b0), "r"(b1));
}
__device__ __forceinline__ float ex2(float x) {
    float y;
    asm("ex2.approx.ftz.f32 %0, %1;" : "=f"(y) : "f"(x));
    return y;
}
__device__ __forceinline__ uint32_t h2pack(float c0, float c1) {
    uint32_t r;
    asm("cvt.rn.f16x2.f32 %0, %1, %2;" : "=r"(r) : "f"(c1), "f"(c0));
    return r;
}
__device__ __forceinline__ uint32_t swz(int r, int c) {
    return (uint32_t)(r * 128 + ((c ^ (r & 7)) << 4));
}

// =================================================================
// single fused fp32 -> fp16 convert: x (1M float4) + 4 W (256K each)
// =================================================================
#define NX4 (ROWS * DM / 4)   // 1048576
#define NW4 (DM * DM / 4)     // 262144

__global__ void __launch_bounds__(256)
conv_all(const float* __restrict__ x,
         const float* __restrict__ w0, const float* __restrict__ w1,
         const float* __restrict__ w2, const float* __restrict__ w3,
         __half* __restrict__ xh, __half* __restrict__ wh)
{
    int i = blockIdx.x * blockDim.x + threadIdx.x;
    const float* src;
    __half* dst;
    int off;
    if (i < NX4) {
        src = x; dst = xh; off = i;
    } else {
        int j = i - NX4;
        int w = j >> 18;
        off = j & (NW4 - 1);
        src = (w == 0) ? w0 : (w == 1) ? w1 : (w == 2) ? w2 : w3;
        dst = wh + (size_t)w * DM * DM;
    }
    float4 v = ((const float4*)src)[off];
    uint2 o;
    o.x = h2pack(v.x, v.y);
    o.y = h2pack(v.z, v.w);
    ((uint2*)dst)[off] = o;
}

// =================================================================
// fp16 HMMA GEMM: CTA 128x128, 4 warps of m64n64, BK=64,
// 3-stage single-sync cp.async pipeline + register frag dbl-buffer.
// =================================================================
#define GBK      64
#define NKC      (DM / GBK)     // 16
#define TILE_B   (128 * 128)    // 16 KB per 128x64-fp16 tile
#define STAGE_B  (2 * TILE_B)   // A tile + W tile
#define GEMM_SMEM (3 * STAGE_B) // 96 KB

// 128 threads: 1024 chunks per 2 tiles -> 8 iters per tile
__device__ __forceinline__ void load_tile128(uint32_t dst, const __half* g,
                                             int row0, int k0, int tid) {
    const char* gb = (const char*)(g + (size_t)row0 * DM + k0);
#pragma unroll
    for (int it = 0; it < 8; it++) {
        int idx = tid + it * 128;
        int r = idx >> 3;
        int c = idx & 7;
        cp16(dst + swz(r, c), gb + (size_t)r * DM * 2 + c * 16);
    }
}

// MODE 0: fp32 C.  MODE 1: fp16 C.
template<int MODE>
__device__ __forceinline__ void hgemm_body(
    const __half* __restrict__ A, const __half* __restrict__ W,
    float* __restrict__ Cf, __half* __restrict__ Ch,
    int m0, int n0, uint32_t sb)
{
    const int tid = threadIdx.x;
    const int wid = tid >> 5;
    const int lane = tid & 31;
    const int wm = wid >> 1;          // 0..1 (64-row slab)
    const int wn = wid & 1;           // 0..1 (64-col slab)
    const int lrow = lane & 15;
    const int lsel = lane >> 4;

    int arow[4], brow[4];
#pragma unroll
    for (int mf = 0; mf < 4; mf++) arow[mf] = wm * 64 + mf * 16 + lrow;
#pragma unroll
    for (int nf = 0; nf < 4; nf++) brow[nf] = wn * 64 + nf * 16 + lrow;

    float acc[4][8][4];
#pragma unroll
    for (int i = 0; i < 4; i++)
#pragma unroll
        for (int j = 0; j < 8; j++)
#pragma unroll
            for (int e = 0; e < 4; e++) acc[i][j][e] = 0.f;

    auto stage = [&](int s) { return sb + s * STAGE_B; };

    // prologue: chunks 0,1 -> stages 0,1
    load_tile128(stage(0) + 0 * TILE_B, A, m0, 0, tid);
    load_tile128(stage(0) + 1 * TILE_B, W, n0, 0, tid);
    CP_COMMIT();
    load_tile128(stage(1) + 0 * TILE_B, A, m0, GBK, tid);
    load_tile128(stage(1) + 1 * TILE_B, W, n0, GBK, tid);
    CP_COMMIT();

    uint32_t af[2][4][4], bf[2][4][4];

    for (int kc = 0; kc < NKC; kc++) {
        if (kc + 1 < NKC) {
            asm volatile("cp.async.wait_group 1;");
        } else {
            asm volatile("cp.async.wait_group 0;");
        }
        __syncthreads();   // single sync: publishes chunk kc, fences stage reuse

        // issue next chunk's loads first so LSU overlaps the MMAs below
        if (kc + 2 < NKC) {
            int s2 = (kc + 2) % 3;
            int k0 = (kc + 2) * GBK;
            load_tile128(stage(s2) + 0 * TILE_B, A, m0, k0, tid);
            load_tile128(stage(s2) + 1 * TILE_B, W, n0, k0, tid);
            CP_COMMIT();
        }

        const uint32_t sA = stage(kc % 3) + 0 * TILE_B;
        const uint32_t sW = stage(kc % 3) + 1 * TILE_B;

        auto ldfrags = [&](int buf, int t) {
            const int c0 = t * 2;
#pragma unroll
            for (int mf = 0; mf < 4; mf++) {
                int r = arow[mf];
                ldsm4(af[buf][mf], sA + (uint32_t)(r * 128 + (((c0 + lsel) ^ (r & 7)) << 4)));
            }
#pragma unroll
            for (int nf = 0; nf < 4; nf++) {
                int r = brow[nf];
                ldsm4(bf[buf][nf], sW + (uint32_t)(r * 128 + (((c0 + lsel) ^ (r & 7)) << 4)));
            }
        };

        ldfrags(0, 0);
#pragma unroll
        for (int t = 0; t < 4; t++) {
            if (t < 3) ldfrags((t + 1) & 1, t + 1);
            const int cb = t & 1;
#pragma unroll
            for (int mf = 0; mf < 4; mf++) {
#pragma unroll
                for (int nf = 0; nf < 4; nf++) {
                    mma_f16(acc[mf][2 * nf],     af[cb][mf], bf[cb][nf][0], bf[cb][nf][2]);
                    mma_f16(acc[mf][2 * nf + 1], af[cb][mf], bf[cb][nf][1], bf[cb][nf][3]);
                }
            }
        }
    }

    const int erow = m0 + wm * 64 + (lane >> 2);
    const int ecol = n0 + wn * 64 + (lane & 3) * 2;
#pragma unroll
    for (int mf = 0; mf < 4; mf++) {
#pragma unroll
        for (int nf = 0; nf < 8; nf++) {
            size_t o0 = (size_t)(erow + mf * 16) * DM + ecol + nf * 8;
            if (MODE == 0) {
                *(float2*)(Cf + o0) = make_float2(acc[mf][nf][0], acc[mf][nf][1]);
                *(float2*)(Cf + o0 + 8 * DM) = make_float2(acc[mf][nf][2], acc[mf][nf][3]);
            } else {
                *(uint32_t*)(Ch + o0) = h2pack(acc[mf][nf][0], acc[mf][nf][1]);
                *(uint32_t*)(Ch + o0 + 8 * DM) = h2pack(acc[mf][nf][2], acc[mf][nf][3]);
            }
        }
    }
}

// fused QKV: grid (24, 32); blockIdx.x selects weight and N tile
__global__ void __launch_bounds__(128, 2)
hgemm_qkv(const __half* __restrict__ A, const __half* __restrict__ Wall,
          __half* __restrict__ q, __half* __restrict__ k, __half* __restrict__ v)
{
    extern __shared__ char smraw[];
    const int wsel = blockIdx.x >> 3;
    const int n0 = (blockIdx.x & 7) * 128;
    const int m0 = blockIdx.y * 128;
    const __half* W = Wall + (size_t)wsel * DM * DM;
    __half* Ch = (wsel == 0) ? q : (wsel == 1) ? k : v;
    hgemm_body<1>(A, W, nullptr, Ch, m0, n0, smem_u32(smraw));
}

// output projection: grid (8, 32)
__global__ void __launch_bounds__(128, 2)
hgemm_o(const __half* __restrict__ A, const __half* __restrict__ W,
        float* __restrict__ Cf)
{
    extern __shared__ char smraw[];
    hgemm_body<0>(A, W, Cf, nullptr, blockIdx.y * 128, blockIdx.x * 128,
                  smem_u32(smraw));
}

// =================================================================
// FlashAttention-2 style causal ALiBi attention, fp16 HMMA (as R7/R8).
// =================================================================
#define AT_Q 128
#define AT_K 64
#define ATT_SMEM (16384 + 32768)

__device__ __forceinline__ void load_kv(uint32_t base,
        const __half* kh, const __half* vh, int b, int h, int kb, int tid)
{
    size_t grow = (size_t)(b * T_ + kb * AT_K) * DM + h * HD;
#pragma unroll
    for (int t = 0; t < 2; t++) {
        int idx = tid + t * 256;
        int r = idx >> 3;
        int c = idx & 7;
        uint32_t sw = swz(r, c);
        size_t off = grow + (size_t)r * DM;
        cp16(base +        sw, (const char*)(kh + off) + c * 16);
        cp16(base + 8192 + sw, (const char*)(vh + off) + c * 16);
    }
}

__global__ void __launch_bounds__(256)
attn_mma(const __half* __restrict__ qh, const __half* __restrict__ kh,
         const __half* __restrict__ vh, __half* __restrict__ oh)
{
    extern __shared__ char smraw[];
    const uint32_t sb = smem_u32(smraw);
    const int tid = threadIdx.x, w = tid >> 5, lane = tid & 31;
    const int h = blockIdx.y, b = blockIdx.z;
    const int i0 = (gridDim.x - 1 - blockIdx.x) * AT_Q;
    const int lrow = lane & 15, lsel = lane >> 4;
    const int rq = lane >> 2, c2 = (lane & 3) * 2;
    const int irow_base = i0 + w * 16;
    const int irow = irow_base + rq;

    const float slope  = ex2(-0.5f * (float)(h + 1));
    const float slope2 = slope * 1.4426950408889634f;
    const float scale2 = 0.18033688011112042f;

    const uint32_t sQ = sb;
    auto stgK = [&](int s) { return sb + 16384 + s * 16384; };

    {
        const char* gq = (const char*)(qh + (size_t)(b * T_ + i0) * DM + h * HD);
#pragma unroll
        for (int t = 0; t < 4; t++) {
            int idx = tid + t * 256;
            int r = idx >> 3;
            int c = idx & 7;
            cp16(sQ + swz(r, c), gq + (size_t)r * DM * 2 + c * 16);
        }
        load_kv(stgK(0), kh, vh, b, h, 0, tid);
        CP_COMMIT();
    }

    uint32_t qf[4][4];
    float O[8][4];
#pragma unroll
    for (int i = 0; i < 8; i++)
#pragma unroll
        for (int e = 0; e < 4; e++) O[i][e] = 0.f;
    float m0 = -1e30f, m1 = -1e30f, l0 = 0.f, l1 = 0.f;

    const int NB = (i0 + AT_Q) / AT_K;

    for (int kb = 0; kb < NB; kb++) {
        int s = kb & 1;
        if (kb + 1 < NB) {
            load_kv(stgK(s ^ 1), kh, vh, b, h, kb + 1, tid);
            CP_COMMIT();
            asm volatile("cp.async.wait_group 1;");
        } else {
            asm volatile("cp.async.wait_group 0;");
        }
        __syncthreads();

        if (kb == 0) {
#pragma unroll
            for (int ks = 0; ks < 4; ks++) {
                int r = w * 16 + lrow;
                uint32_t off = (uint32_t)(r * 128 + (((2 * ks + lsel) ^ (r & 7)) << 4));
                ldsm4(qf[ks], sQ + off);
            }
        }

        if (kb * AT_K <= irow_base + 15) {
            const uint32_t sK = stgK(s), sV = sK + 8192;

            float S[8][4];
#pragma unroll
            for (int i = 0; i < 8; i++)
#pragma unroll
                for (int e = 0; e < 4; e++) S[i][e] = 0.f;

#pragma unroll
            for (int ks = 0; ks < 4; ks++) {
#pragma unroll
                for (int np = 0; np < 4; np++) {
                    int r = np * 16 + lrow;
                    uint32_t off = (uint32_t)(r * 128 + (((2 * ks + lsel) ^ (r & 7)) << 4));
                    uint32_t bh[4];
                    ldsm4(bh, sK + off);
                    mma_f16(S[2 * np],     qf[ks], bh[0], bh[2]);
                    mma_f16(S[2 * np + 1], qf[ks], bh[1], bh[3]);
                }
            }

            const int jb = kb * AT_K + c2;
            const bool nomask = (kb * AT_K + 63) <= irow_base;
            float rm0 = -1e30f, rm1 = -1e30f;
#pragma unroll
            for (int nf = 0; nf < 8; nf++) {
                int d0 = irow - (jb + 8 * nf);
                float fd = (float)d0;
                float bia = -slope2 * fd;
                float t0 = fmaf(S[nf][0], scale2, bia);
                float t1 = fmaf(S[nf][1], scale2, bia + slope2);
                float t2 = fmaf(S[nf][2], scale2, bia - 8.f * slope2);
                float t3 = fmaf(S[nf][3], scale2, bia - 7.f * slope2);
                if (!nomask) {
                    t0 = (d0 >= 0)  ? t0 : -1e30f;
                    t1 = (d0 >= 1)  ? t1 : -1e30f;
                    t2 = (d0 >= -8) ? t2 : -1e30f;
                    t3 = (d0 >= -7) ? t3 : -1e30f;
                }
                S[nf][0] = t0; S[nf][1] = t1; S[nf][2] = t2; S[nf][3] = t3;
                rm0 = fmaxf(rm0, fmaxf(t0, t1));
                rm1 = fmaxf(rm1, fmaxf(t2, t3));
            }
            rm0 = fmaxf(rm0, __shfl_xor_sync(0xffffffffu, rm0, 1));
            rm0 = fmaxf(rm0, __shfl_xor_sync(0xffffffffu, rm0, 2));
            rm1 = fmaxf(rm1, __shfl_xor_sync(0xffffffffu, rm1, 1));
            rm1 = fmaxf(rm1, __shfl_xor_sync(0xffffffffu, rm1, 2));

            float m0n = fmaxf(m0, rm0), m1n = fmaxf(m1, rm1);
            float cr0 = ex2(m0 - m0n), cr1 = ex2(m1 - m1n);
            m0 = m0n; m1 = m1n;
            l0 *= cr0; l1 *= cr1;
#pragma unroll
            for (int nf = 0; nf < 8; nf++) {
                O[nf][0] *= cr0; O[nf][1] *= cr0;
                O[nf][2] *= cr1; O[nf][3] *= cr1;
            }
#pragma unroll
            for (int nf = 0; nf < 8; nf++) {
                float p0 = ex2(S[nf][0] - m0);
                float p1 = ex2(S[nf][1] - m0);
                float p2 = ex2(S[nf][2] - m1);
                float p3 = ex2(S[nf][3] - m1);
                S[nf][0] = p0; S[nf][1] = p1; S[nf][2] = p2; S[nf][3] = p3;
                l0 += p0 + p1;
                l1 += p2 + p3;
            }

#pragma unroll
            for (int ks2 = 0; ks2 < 4; ks2++) {
                uint32_t af2[4];
                af2[0] = h2pack(S[2 * ks2][0],     S[2 * ks2][1]);
                af2[1] = h2pack(S[2 * ks2][2],     S[2 * ks2][3]);
                af2[2] = h2pack(S[2 * ks2 + 1][0], S[2 * ks2 + 1][1]);
                af2[3] = h2pack(S[2 * ks2 + 1][2], S[2 * ks2 + 1][3]);
#pragma unroll
                for (int nf2 = 0; nf2 < 4; nf2++) {
                    int r = ks2 * 16 + lrow;
                    uint32_t off = (uint32_t)(r * 128 + (((2 * nf2 + lsel) ^ (r & 7)) << 4));
                    uint32_t bh[4];
                    ldsm4t(bh, sV + off);
                    mma_f16(O[2 * nf2],     af2, bh[0], bh[1]);
                    mma_f16(O[2 * nf2 + 1], af2, bh[2], bh[3]);
                }
            }
        }
        __syncthreads();
    }

    l0 += __shfl_xor_sync(0xffffffffu, l0, 1);
    l0 += __shfl_xor_sync(0xffffffffu, l0, 2);
    l1 += __shfl_xor_sync(0xffffffffu, l1, 1);
    l1 += __shfl_xor_sync(0xffffffffu, l1, 2);
    float iv0 = 1.0f / l0, iv1 = 1.0f / l1;

    size_t obase = (size_t)(b * T_ + irow) * DM + h * HD + c2;
#pragma unroll
    for (int nf = 0; nf < 8; nf++) {
        *(uint32_t*)(oh + obase + 8 * nf) =
            h2pack(O[nf][0] * iv0, O[nf][1] * iv0);
        *(uint32_t*)(oh + obase + 8 * DM + 8 * nf) =
            h2pack(O[nf][2] * iv1, O[nf][3] * iv1);
    }
}

// =================================================================
extern "C" void kernel_launch(void* const* d_in, const int* in_sizes, int n_in,
                              void* d_out, int out_size)
{
    const float* x  = (const float*)d_in[0];
    const float* Wq = (const float*)d_in[1];
    const float* Wk = (const float*)d_in[2];
    const float* Wv = (const float*)d_in[3];
    const float* Wo = (const float*)d_in[4];
    float* out = (float*)d_out;

    __half *xh, *wh, *qh, *kh, *vh, *ah;
    cudaGetSymbolAddress((void**)&xh, g_xh);
    cudaGetSymbolAddress((void**)&wh, g_wh);
    cudaGetSymbolAddress((void**)&qh, g_qh);
    cudaGetSymbolAddress((void**)&kh, g_kh);
    cudaGetSymbolAddress((void**)&vh, g_vh);
    cudaGetSymbolAddress((void**)&ah, g_ah);

    cudaFuncSetAttribute(hgemm_qkv,
                         cudaFuncAttributeMaxDynamicSharedMemorySize, GEMM_SMEM);
    cudaFuncSetAttribute(hgemm_o,
                         cudaFuncAttributeMaxDynamicSharedMemorySize, GEMM_SMEM);
    cudaFuncSetAttribute(attn_mma,
                         cudaFuncAttributeMaxDynamicSharedMemorySize, ATT_SMEM);

    conv_all<<<(NX4 + 4 * NW4) / 256, 256>>>(x, Wq, Wk, Wv, Wo, xh, wh);

    hgemm_qkv<<<dim3(24, ROWS / 128), 128, GEMM_SMEM>>>(xh, wh, qh, kh, vh);

    dim3 agrid(T_ / AT_Q, H_, B_);      // (16, 16, 2)
    attn_mma<<<agrid, 256, ATT_SMEM>>>(qh, kh, vh, ah);

    hgemm_o<<<dim3(DM / 128, ROWS / 128), 128, GEMM_SMEM>>>(
        ah, wh + 3 * (size_t)DM * DM, out);
}